// round 8
// baseline (speedup 1.0000x reference)
#include <cuda_runtime.h>
#include <cuda_bf16.h>
#include <mma.h>
#include <cstdint>
using namespace nvcuda;
typedef __nv_bfloat16 bf;

#define N_TOK 2048
#define EDIM  768
#define HEADS 12
#define DH    64
#define LAYW  (EDIM * EDIM)

// fp32 scratch
__device__ float g_x[N_TOK * EDIM], g_mh[EDIM * N_TOK], g_l1[N_TOK * EDIM], g_ffn[N_TOK * EDIM];
// bf16 split activations
__device__ bf g_xh[N_TOK * EDIM], g_xl[N_TOK * EDIM], g_qh[N_TOK * EDIM], g_ql[N_TOK * EDIM],
              g_l1h[N_TOK * EDIM], g_l1l[N_TOK * EDIM], g_zth[N_TOK * EDIM], g_ztl[N_TOK * EDIM];
// bf16 split weights, all 12 layers
__device__ bf g_wqh[12 * LAYW], g_wql[12 * LAYW], g_woh[12 * LAYW], g_wol[12 * LAYW],
              g_fwh[12 * LAYW], g_fwl[12 * LAYW];

// ---------------- helpers ----------------
__device__ __forceinline__ uint32_t smem_u32(const void* p) {
    uint32_t a;
    asm("{ .reg .u64 t; cvta.to.shared.u64 t, %1; cvt.u32.u64 %0, t; }" : "=r"(a) : "l"(p));
    return a;
}
__device__ __forceinline__ uint32_t pk2(float lo, float hi) {
    uint32_t r;
    asm("cvt.rn.bf16x2.f32 %0, %1, %2;" : "=r"(r) : "f"(hi), "f"(lo));
    return r;
}
__device__ __forceinline__ void split1(float v, bf* h, bf* l) {
    bf hh = __float2bfloat16(v);
    *h = hh;
    *l = __float2bfloat16(v - __bfloat162float(hh));
}
__device__ __forceinline__ void mma16816(float* c, const uint32_t* a, uint32_t b0, uint32_t b1) {
    asm volatile("mma.sync.aligned.m16n8k16.row.col.f32.bf16.bf16.f32 "
                 "{%0,%1,%2,%3}, {%4,%5,%6,%7}, {%8,%9}, {%0,%1,%2,%3};"
                 : "+f"(c[0]), "+f"(c[1]), "+f"(c[2]), "+f"(c[3])
                 : "r"(a[0]), "r"(a[1]), "r"(a[2]), "r"(a[3]), "r"(b0), "r"(b1));
}
__device__ __forceinline__ void ldm4(uint32_t* r, uint32_t addr) {
    asm volatile("ldmatrix.sync.aligned.m8n8.x4.shared.b16 {%0,%1,%2,%3}, [%4];"
                 : "=r"(r[0]), "=r"(r[1]), "=r"(r[2]), "=r"(r[3]) : "r"(addr));
}
__device__ __forceinline__ void ldm4t(uint32_t* r, uint32_t addr) {
    asm volatile("ldmatrix.sync.aligned.m8n8.x4.trans.shared.b16 {%0,%1,%2,%3}, [%4];"
                 : "=r"(r[0]), "=r"(r[1]), "=r"(r[2]), "=r"(r[3]) : "r"(addr));
}
#define CPA(dst, src) asm volatile("cp.async.cg.shared.global [%0], [%1], 16;" :: "r"(dst), "l"(src))
#define CPC()  asm volatile("cp.async.commit_group;" ::: "memory")
#define CPW0() asm volatile("cp.async.wait_group 0;" ::: "memory")
#define CPW1() asm volatile("cp.async.wait_group 1;" ::: "memory")

// ---------------- prep kernels ----------------
__global__ void prep_wq(const float* __restrict__ wq, bf* __restrict__ oh, bf* __restrict__ ol) {
    int idx = blockIdx.x * 256 + threadIdx.x;          // 12*768*768
    int lay = idx / LAYW, r = idx % LAYW;
    int n = r / EDIM, e = r % EDIM;
    float v = wq[(size_t)lay * LAYW + (n >> 6) * (EDIM * DH) + e * DH + (n & 63)];
    split1(v, &oh[idx], &ol[idx]);
}
__global__ void split_arr(const float* __restrict__ s, bf* __restrict__ oh, bf* __restrict__ ol) {
    int idx = blockIdx.x * 256 + threadIdx.x;
    split1(s[idx], &oh[idx], &ol[idx]);
}
__global__ void add_pe_kernel(const float* __restrict__ tokens, float* __restrict__ x,
                              bf* __restrict__ xh, bf* __restrict__ xl) {
    int idx = blockIdx.x * 256 + threadIdx.x;
    int e = idx % EDIM, n = idx / EDIM, s = n & 511;
    float p = (e < 384) ? 10000.0f : 10001.0f;
    float ang = (float)s / p;
    float pe = (e & 1) ? cosf(ang) : sinf(ang);
    float v = tokens[idx] + pe;
    x[idx] = v;
    split1(v, &xh[idx], &xl[idx]);
}

// ---------------- bf16-split GEMM: D[M,N] = A[M,K]*B[N,K]^T ----------------
// 64(M) x 128(N) CTA tile, 8 warps (2x4), warp 32x32, K chunk 64,
// double-buffered cp.async, 2 CTAs/SM, grid 192 for all three GEMMs.
#define GP 72
#define GA (64 * GP)
#define GB (128 * GP)
#define STG (2 * GA + 2 * GB)            // elems per stage (Ah,Al,Bh,Bl)
#define GEMM_SMEM (2 * STG * 2)          // 110592 bytes

__device__ __forceinline__ void gemm_load(uint32_t sb, int b, const bf* Ah, const bf* Al,
                                          const bf* Bh, const bf* Bl,
                                          int bm, int bn, int K, int k0, int tid) {
    uint32_t base = sb + (uint32_t)(b * STG) * 2;
#pragma unroll
    for (int m = 0; m < 2; m++) {
        int task = tid + 256 * m;
        int r = task >> 3, gc = (task & 7) * 8;
        uint32_t so = (uint32_t)(r * GP + gc) * 2;
        size_t ga = (size_t)(bm + r) * K + k0 + gc;
        CPA(base + so,          Ah + ga);
        CPA(base + GA * 2 + so, Al + ga);
    }
#pragma unroll
    for (int m = 0; m < 4; m++) {
        int task = tid + 256 * m;
        int r = task >> 3, gc = (task & 7) * 8;
        uint32_t so = (uint32_t)(r * GP + gc) * 2;
        size_t gb = (size_t)(bn + r) * K + k0 + gc;
        CPA(base + 4 * GA + so,          Bh + gb);
        CPA(base + (4 * GA + 2 * GB) + so, Bl + gb);
    }
    CPC();
}

template <bool OUTSPLIT>
__global__ void __launch_bounds__(256, 2)
gemm_bf(const bf* __restrict__ Ah, const bf* __restrict__ Al,
        const bf* __restrict__ Bh, const bf* __restrict__ Bl,
        float* __restrict__ C, bf* __restrict__ Ch, bf* __restrict__ Cl,
        int M, int N, int K) {
    extern __shared__ bf ds[];
    uint32_t sb = smem_u32(ds);
    int tid = threadIdx.x, wid = tid >> 5;
    int bm = blockIdx.y * 64, bn = blockIdx.x * 128;
    int wm = (wid & 1) * 32, wn = (wid >> 1) * 32;

    wmma::fragment<wmma::accumulator, 16, 16, 16, float> acc[2][2];
#pragma unroll
    for (int i = 0; i < 2; i++)
#pragma unroll
        for (int j = 0; j < 2; j++) wmma::fill_fragment(acc[i][j], 0.f);

    const int NCH = K / 64;
    gemm_load(sb, 0, Ah, Al, Bh, Bl, bm, bn, K, 0, tid);

    for (int c = 0; c < NCH; c++) {
        if (c + 1 < NCH) {
            gemm_load(sb, (c + 1) & 1, Ah, Al, Bh, Bl, bm, bn, K, (c + 1) * 64, tid);
            CPW1();
        } else {
            CPW0();
        }
        __syncthreads();
        bf* Ahs = ds + (size_t)(c & 1) * STG;
        bf* Als = Ahs + GA;
        bf* Bhs = Ahs + 2 * GA;
        bf* Bls = Ahs + 2 * GA + GB;
#pragma unroll
        for (int kc = 0; kc < 4; kc++) {
            wmma::fragment<wmma::matrix_a, 16, 16, 16, bf, wmma::row_major> ah2[2], al2[2];
#pragma unroll
            for (int i = 0; i < 2; i++) {
                wmma::load_matrix_sync(ah2[i], &Ahs[(wm + 16 * i) * GP + kc * 16], GP);
                wmma::load_matrix_sync(al2[i], &Als[(wm + 16 * i) * GP + kc * 16], GP);
            }
#pragma unroll
            for (int j = 0; j < 2; j++) {
                wmma::fragment<wmma::matrix_b, 16, 16, 16, bf, wmma::col_major> bh2, bl2;
                wmma::load_matrix_sync(bh2, &Bhs[(wn + 16 * j) * GP + kc * 16], GP);
                wmma::load_matrix_sync(bl2, &Bls[(wn + 16 * j) * GP + kc * 16], GP);
#pragma unroll
                for (int i = 0; i < 2; i++) {
                    wmma::mma_sync(acc[i][j], ah2[i], bh2, acc[i][j]);
                    wmma::mma_sync(acc[i][j], ah2[i], bl2, acc[i][j]);
                    wmma::mma_sync(acc[i][j], al2[i], bh2, acc[i][j]);
                }
            }
        }
        __syncthreads();
    }

    if (!OUTSPLIT) {
#pragma unroll
        for (int i = 0; i < 2; i++)
#pragma unroll
            for (int j = 0; j < 2; j++)
                wmma::store_matrix_sync(&C[(size_t)(bm + wm + 16 * i) * N + bn + wn + 16 * j],
                                        acc[i][j], N, wmma::mem_row_major);
    } else {
        float* cs = (float*)ds;                   // 64x128 fp32 staging (32KB)
#pragma unroll
        for (int i = 0; i < 2; i++)
#pragma unroll
            for (int j = 0; j < 2; j++)
                wmma::store_matrix_sync(&cs[(wm + 16 * i) * 128 + wn + 16 * j],
                                        acc[i][j], 128, wmma::mem_row_major);
        __syncthreads();
#pragma unroll
        for (int m = 0; m < 32; m++) {
            int idx = tid + 256 * m;
            int r = idx >> 7, cc = idx & 127;
            size_t go = (size_t)(bm + r) * N + bn + cc;
            split1(cs[r * 128 + cc], &Ch[go], &Cl[go]);
        }
    }
}

// ---------------- flash attention (q==k==v), pre-split bf16, cp.async pipeline ----------------
// Epilogue writes the TRANSPOSED split output zth/ztl [2048 x 768] directly:
// this CTA (h, rb) owns zcT columns h*64+2rb and h*64+2rb+1 across all 2048 rows.
#define FP 72
#define FQH 0
#define FQL (64 * FP)
#define FKH(b) (2 * 64 * FP + (b) * 2 * 64 * FP)
#define FKL(b) (FKH(b) + 64 * FP)
#define FLASH_SMEM (6 * 64 * FP * 2)

__global__ void __launch_bounds__(128, 3)
flash_bf(const bf* __restrict__ Qh, const bf* __restrict__ Ql,
         bf* __restrict__ zth, bf* __restrict__ ztl) {
    extern __shared__ bf ds[];
    uint32_t sb = smem_u32(ds);
    int tid = threadIdx.x, lane = tid & 31, wid = tid >> 5;
    int h = blockIdx.y, rb = blockIdx.x;
    size_t hoff = (size_t)h * DH;

#pragma unroll
    for (int m = 0; m < 4; m++) {
        int task = tid + 128 * m;
        int r = task >> 3, gc = (task & 7) * 8;
        size_t go = (size_t)(rb * 64 + r) * EDIM + hoff + gc;
        CPA(sb + (FQH + r * FP + gc) * 2, Qh + go);
        CPA(sb + (FQL + r * FP + gc) * 2, Ql + go);
        size_t gk = (size_t)r * EDIM + hoff + gc;
        CPA(sb + (FKH(0) + r * FP + gc) * 2, Qh + gk);
        CPA(sb + (FKL(0) + r * FP + gc) * 2, Ql + gk);
    }
    CPC(); CPW0();
    __syncthreads();

    int ar = wid * 16 + (lane >> 2);
    int ac = 2 * (lane & 3);
    uint32_t qah[4][4], qal[4][4];
#pragma unroll
    for (int kc = 0; kc < 4; kc++) {
        int cb = kc * 16 + ac;
        qah[kc][0] = *(uint32_t*)&ds[FQH + (ar)     * FP + cb];
        qah[kc][1] = *(uint32_t*)&ds[FQH + (ar + 8) * FP + cb];
        qah[kc][2] = *(uint32_t*)&ds[FQH + (ar)     * FP + cb + 8];
        qah[kc][3] = *(uint32_t*)&ds[FQH + (ar + 8) * FP + cb + 8];
        qal[kc][0] = *(uint32_t*)&ds[FQL + (ar)     * FP + cb];
        qal[kc][1] = *(uint32_t*)&ds[FQL + (ar + 8) * FP + cb];
        qal[kc][2] = *(uint32_t*)&ds[FQL + (ar)     * FP + cb + 8];
        qal[kc][3] = *(uint32_t*)&ds[FQL + (ar + 8) * FP + cb + 8];
    }

    float m0 = -1e30f, m1 = -1e30f, l0 = 0.f, l1 = 0.f;
    float o[8][4];
#pragma unroll
    for (int j = 0; j < 8; j++)
#pragma unroll
        for (int c = 0; c < 4; c++) o[j][c] = 0.f;

    int g = lane >> 3, i8 = lane & 7;
    uint32_t offS = (uint32_t)(((g >> 1) * 8 + i8) * FP + (g & 1) * 8) * 2;
    uint32_t offV = (uint32_t)(((g & 1) * 8 + i8) * FP + (g >> 1) * 8) * 2;

    for (int ct = 0; ct < 32; ct++) {
        if (ct < 31) {
            int b = (ct + 1) & 1;
#pragma unroll
            for (int m = 0; m < 4; m++) {
                int task = tid + 128 * m;
                int r = task >> 3, gc = (task & 7) * 8;
                size_t gk = (size_t)((ct + 1) * 64 + r) * EDIM + hoff + gc;
                CPA(sb + (FKH(b) + r * FP + gc) * 2, Qh + gk);
                CPA(sb + (FKL(b) + r * FP + gc) * 2, Ql + gk);
            }
            CPC(); CPW1();
        } else {
            CPW0();
        }
        __syncthreads();
        uint32_t khb = sb + FKH(ct & 1) * 2, klb = sb + FKL(ct & 1) * 2;

        float sacc[8][4];
#pragma unroll
        for (int j = 0; j < 8; j++)
#pragma unroll
            for (int c = 0; c < 4; c++) sacc[j][c] = 0.f;
#pragma unroll
        for (int kc = 0; kc < 4; kc++) {
#pragma unroll
            for (int jp = 0; jp < 4; jp++) {
                uint32_t toff = (uint32_t)(jp * 16 * FP + kc * 16) * 2;
                uint32_t bh[4], bl[4];
                ldm4(bh, khb + offS + toff);
                ldm4(bl, klb + offS + toff);
                mma16816(sacc[2 * jp],     qah[kc], bh[0], bh[1]);
                mma16816(sacc[2 * jp],     qah[kc], bl[0], bl[1]);
                mma16816(sacc[2 * jp],     qal[kc], bh[0], bh[1]);
                mma16816(sacc[2 * jp + 1], qah[kc], bh[2], bh[3]);
                mma16816(sacc[2 * jp + 1], qah[kc], bl[2], bl[3]);
                mma16816(sacc[2 * jp + 1], qal[kc], bh[2], bh[3]);
            }
        }

        float mx0 = -1e30f, mx1 = -1e30f;
#pragma unroll
        for (int j = 0; j < 8; j++) {
#pragma unroll
            for (int c = 0; c < 4; c++) sacc[j][c] *= 0.125f;
            mx0 = fmaxf(mx0, fmaxf(sacc[j][0], sacc[j][1]));
            mx1 = fmaxf(mx1, fmaxf(sacc[j][2], sacc[j][3]));
        }
        mx0 = fmaxf(mx0, __shfl_xor_sync(0xffffffffu, mx0, 1));
        mx0 = fmaxf(mx0, __shfl_xor_sync(0xffffffffu, mx0, 2));
        mx1 = fmaxf(mx1, __shfl_xor_sync(0xffffffffu, mx1, 1));
        mx1 = fmaxf(mx1, __shfl_xor_sync(0xffffffffu, mx1, 2));
        float mn0 = fmaxf(m0, mx0), mn1 = fmaxf(m1, mx1);
        float al0 = __expf(m0 - mn0), al1 = __expf(m1 - mn1);

        float rs0 = 0.f, rs1 = 0.f;
        uint32_t pah[4][4], pal[4][4];
#pragma unroll
        for (int j = 0; j < 8; j++) {
            float p0 = __expf(sacc[j][0] - mn0);
            float p1 = __expf(sacc[j][1] - mn0);
            float p2 = __expf(sacc[j][2] - mn1);
            float p3 = __expf(sacc[j][3] - mn1);
            rs0 += p0 + p1; rs1 += p2 + p3;
            float f0 = __bfloat162float(__float2bfloat16(p0));
            float f1 = __bfloat162float(__float2bfloat16(p1));
            float f2 = __bfloat162float(__float2bfloat16(p2));
            float f3 = __bfloat162float(__float2bfloat16(p3));
            int kc = j >> 1, off = (j & 1) * 2;
            pah[kc][off]     = pk2(p0, p1);
            pah[kc][off + 1] = pk2(p2, p3);
            pal[kc][off]     = pk2(p0 - f0, p1 - f1);
            pal[kc][off + 1] = pk2(p2 - f2, p3 - f3);
        }
        rs0 += __shfl_xor_sync(0xffffffffu, rs0, 1);
        rs0 += __shfl_xor_sync(0xffffffffu, rs0, 2);
        rs1 += __shfl_xor_sync(0xffffffffu, rs1, 1);
        rs1 += __shfl_xor_sync(0xffffffffu, rs1, 2);
        l0 = l0 * al0 + rs0;
        l1 = l1 * al1 + rs1;
        m0 = mn0; m1 = mn1;
#pragma unroll
        for (int j = 0; j < 8; j++) {
            o[j][0] *= al0; o[j][1] *= al0;
            o[j][2] *= al1; o[j][3] *= al1;
        }

#pragma unroll
        for (int kc = 0; kc < 4; kc++) {
#pragma unroll
            for (int jdp = 0; jdp < 4; jdp++) {
                uint32_t toff = (uint32_t)(kc * 16 * FP + jdp * 16) * 2;
                uint32_t vh[4], vl[4];
                ldm4t(vh, khb + offV + toff);
                ldm4t(vl, klb + offV + toff);
                mma16816(o[2 * jdp],     pah[kc], vh[0], vh[1]);
                mma16816(o[2 * jdp],     pah[kc], vl[0], vl[1]);
                mma16816(o[2 * jdp],     pal[kc], vh[0], vh[1]);
                mma16816(o[2 * jdp + 1], pah[kc], vh[2], vh[3]);
                mma16816(o[2 * jdp + 1], pah[kc], vl[2], vl[3]);
                mma16816(o[2 * jdp + 1], pal[kc], vh[2], vh[3]);
            }
        }
        __syncthreads();
    }

    // ---- epilogue: stage O (scaled) in smem, then write transposed split output ----
    const int SOP = 68;                              // fp32 staging pitch
    float* sO = (float*)ds;                          // 64x68 fp32 = 17.4KB (Q region)
    float inv0 = 1.f / l0, inv1 = 1.f / l1;
#pragma unroll
    for (int jd = 0; jd < 8; jd++) {
        int d = jd * 8 + ac;
        sO[ar * SOP + d]           = o[jd][0] * inv0;
        sO[ar * SOP + d + 1]       = o[jd][1] * inv0;
        sO[(ar + 8) * SOP + d]     = o[jd][2] * inv1;
        sO[(ar + 8) * SOP + d + 1] = o[jd][3] * inv1;
    }
    __syncthreads();
    int cb = h * 64 + 2 * rb;                        // two adjacent zcT columns
#pragma unroll
    for (int m = 0; m < 16; m++) {
        int r2 = tid + 128 * m;                      // 0..2047: zcT row = (n&31)*64 + d
        int j = r2 >> 6, d = r2 & 63;
        float vlo = sO[j * SOP + d];                 // token group n>>5 == 2*rb
        float vhi = sO[(j + 32) * SOP + d];          // token group n>>5 == 2*rb+1
        bf h0 = __float2bfloat16(vlo), h1 = __float2bfloat16(vhi);
        float r0 = vlo - __bfloat162float(h0), r1 = vhi - __bfloat162float(h1);
        uint32_t ph = ((uint32_t)*(uint16_t*)&h1 << 16) | *(uint16_t*)&h0;
        bf e0 = __float2bfloat16(r0), e1 = __float2bfloat16(r1);
        uint32_t pl = ((uint32_t)*(uint16_t*)&e1 << 16) | *(uint16_t*)&e0;
        size_t go = (size_t)r2 * EDIM + cb;
        *(uint32_t*)&zth[go] = ph;
        *(uint32_t*)&ztl[go] = pl;
    }
}

// ---------------- fused residual (+bias) + LayerNorm (+optional split out) ----------------
template <bool SPLIT>
__global__ void add_ln(const float* __restrict__ A, const float* __restrict__ Bd,
                       const float* __restrict__ g, const float* __restrict__ bb,
                       const float* __restrict__ extra, float* __restrict__ out,
                       bf* __restrict__ oh, bf* __restrict__ ol) {
    __shared__ float red[8];
    int n = blockIdx.x, tid = threadIdx.x;
    float loc[3];
    float s = 0.f;
#pragma unroll
    for (int i = 0; i < 3; i++) {
        int e = tid + i * 256;
        float v = A[(size_t)n * EDIM + e] + Bd[(size_t)n * EDIM + e];
        if (extra) v += extra[e];
        loc[i] = v; s += v;
    }
#pragma unroll
    for (int o = 16; o; o >>= 1) s += __shfl_xor_sync(0xffffffffu, s, o);
    if ((tid & 31) == 0) red[tid >> 5] = s;
    __syncthreads();
    if (tid < 32) {
        float t = (tid < 8) ? red[tid] : 0.f;
#pragma unroll
        for (int o = 4; o; o >>= 1) t += __shfl_xor_sync(0xffffffffu, t, o);
        if (tid == 0) red[0] = t;
    }
    __syncthreads();
    float mu = red[0] * (1.f / 768.f);
    __syncthreads();
    float sq = 0.f;
#pragma unroll
    for (int i = 0; i < 3; i++) { float d = loc[i] - mu; sq += d * d; }
#pragma unroll
    for (int o = 16; o; o >>= 1) sq += __shfl_xor_sync(0xffffffffu, sq, o);
    if ((tid & 31) == 0) red[tid >> 5] = sq;
    __syncthreads();
    if (tid < 32) {
        float t = (tid < 8) ? red[tid] : 0.f;
#pragma unroll
        for (int o = 4; o; o >>= 1) t += __shfl_xor_sync(0xffffffffu, t, o);
        if (tid == 0) red[0] = t;
    }
    __syncthreads();
    float var = red[0] * (1.f / 768.f);
    float inv = rsqrtf(var + 1e-5f);
#pragma unroll
    for (int i = 0; i < 3; i++) {
        int e = tid + i * 256;
        float v = (loc[i] - mu) * inv * g[e] + bb[e];
        size_t go = (size_t)n * EDIM + e;
        out[go] = v;
        if (SPLIT) split1(v, &oh[go], &ol[go]);
    }
}

// ---------------- launch ----------------
extern "C" void kernel_launch(void* const* d_in, const int* in_sizes, int n_in,
                              void* d_out, int out_size) {
    const float* tokens = (const float*)d_in[0];
    const float* wq = (const float*)d_in[1];
    const float* wo = (const float*)d_in[2];
    const float* g1 = (const float*)d_in[3];
    const float* b1 = (const float*)d_in[4];
    const float* fw = (const float*)d_in[5];
    const float* fb = (const float*)d_in[6];
    const float* g2 = (const float*)d_in[7];
    const float* b2 = (const float*)d_in[8];
    float* out = (float*)d_out;

    float *x, *mh, *l1, *ffn;
    bf *xh, *xl, *qh, *ql, *l1h, *l1l, *zth, *ztl;
    bf *wqh, *wql, *woh, *wol, *fwh, *fwl;
    cudaGetSymbolAddress((void**)&x, g_x);     cudaGetSymbolAddress((void**)&mh, g_mh);
    cudaGetSymbolAddress((void**)&l1, g_l1);   cudaGetSymbolAddress((void**)&ffn, g_ffn);
    cudaGetSymbolAddress((void**)&xh, g_xh);   cudaGetSymbolAddress((void**)&xl, g_xl);
    cudaGetSymbolAddress((void**)&qh, g_qh);   cudaGetSymbolAddress((void**)&ql, g_ql);
    cudaGetSymbolAddress((void**)&l1h, g_l1h); cudaGetSymbolAddress((void**)&l1l, g_l1l);
    cudaGetSymbolAddress((void**)&zth, g_zth); cudaGetSymbolAddress((void**)&ztl, g_ztl);
    cudaGetSymbolAddress((void**)&wqh, g_wqh); cudaGetSymbolAddress((void**)&wql, g_wql);
    cudaGetSymbolAddress((void**)&woh, g_woh); cudaGetSymbolAddress((void**)&wol, g_wol);
    cudaGetSymbolAddress((void**)&fwh, g_fwh); cudaGetSymbolAddress((void**)&fwl, g_fwl);

    cudaFuncSetAttribute(gemm_bf<false>, cudaFuncAttributeMaxDynamicSharedMemorySize, GEMM_SMEM);
    cudaFuncSetAttribute(gemm_bf<true>,  cudaFuncAttributeMaxDynamicSharedMemorySize, GEMM_SMEM);
    cudaFuncSetAttribute(flash_bf, cudaFuncAttributeMaxDynamicSharedMemorySize, FLASH_SMEM);

    prep_wq<<<12 * LAYW / 256, 256>>>(wq, wqh, wql);
    split_arr<<<12 * LAYW / 256, 256>>>(wo, woh, wol);
    split_arr<<<12 * LAYW / 256, 256>>>(fw, fwh, fwl);
    add_pe_kernel<<<(N_TOK * EDIM) / 256, 256>>>(tokens, x, xh, xl);

    for (int step = 0; step < 13; step++) {
        int lidx = (step == 0) ? 0 : step - 1;
        const bf* wqh_l = wqh + (size_t)lidx * LAYW;
        const bf* wql_l = wql + (size_t)lidx * LAYW;
        const bf* woh_l = woh + (size_t)lidx * LAYW;
        const bf* wol_l = wol + (size_t)lidx * LAYW;
        const bf* fwh_l = fwh + (size_t)lidx * LAYW;
        const bf* fwl_l = fwl + (size_t)lidx * LAYW;

        // q = x @ wqfT^T  -> split bf16 output directly   [2048x768], grid 192
        gemm_bf<true><<<dim3(EDIM / 128, N_TOK / 64), 256, GEMM_SMEM>>>(
            xh, xl, wqh_l, wql_l, nullptr, qh, ql, N_TOK, EDIM, EDIM);

        // attention -> zth/ztl (transposed split output written directly)
        flash_bf<<<dim3(32, HEADS), 128, FLASH_SMEM>>>(qh, ql, zth, ztl);

        // mh = wo @ zcT^T   [768x2048], grid 192
        gemm_bf<false><<<dim3(N_TOK / 128, EDIM / 64), 256, GEMM_SMEM>>>(
            woh_l, wol_l, zth, ztl, mh, nullptr, nullptr, EDIM, N_TOK, EDIM);

        add_ln<true><<<N_TOK, 256>>>(x, mh, g1 + lidx * EDIM, b1 + lidx * EDIM,
                                     nullptr, l1, l1h, l1l);

        // ffn = l1 @ fw^T (bias folded into next add_ln)   [2048x768], grid 192
        gemm_bf<false><<<dim3(EDIM / 128, N_TOK / 64), 256, GEMM_SMEM>>>(
            l1h, l1l, fwh_l, fwl_l, ffn, nullptr, nullptr, N_TOK, EDIM, EDIM);

        if (step == 12)
            add_ln<false><<<N_TOK, 256>>>(l1, ffn, g2 + lidx * EDIM, b2 + lidx * EDIM,
                                          fb + lidx * EDIM, out, nullptr, nullptr);
        else
            add_ln<true><<<N_TOK, 256>>>(l1, ffn, g2 + lidx * EDIM, b2 + lidx * EDIM,
                                         fb + lidx * EDIM, x, xh, xl);
    }
}

// round 9
// speedup vs baseline: 1.0239x; 1.0239x over previous
#include <cuda_runtime.h>
#include <cuda_bf16.h>
#include <mma.h>
#include <cstdint>
using namespace nvcuda;
typedef __nv_bfloat16 bf;

#define N_TOK 2048
#define EDIM  768
#define HEADS 12
#define DH    64
#define LAYW  (EDIM * EDIM)

// fp32 scratch
__device__ float g_x[N_TOK * EDIM], g_mh[EDIM * N_TOK], g_l1[N_TOK * EDIM], g_ffn[N_TOK * EDIM];
// bf16 split activations
__device__ bf g_xh[N_TOK * EDIM], g_xl[N_TOK * EDIM], g_qh[N_TOK * EDIM], g_ql[N_TOK * EDIM],
              g_l1h[N_TOK * EDIM], g_l1l[N_TOK * EDIM], g_zth[N_TOK * EDIM], g_ztl[N_TOK * EDIM];
// bf16 split weights, all 12 layers
__device__ bf g_wqh[12 * LAYW], g_wql[12 * LAYW], g_woh[12 * LAYW], g_wol[12 * LAYW],
              g_fwh[12 * LAYW], g_fwl[12 * LAYW];

// ---------------- helpers ----------------
__device__ __forceinline__ uint32_t smem_u32(const void* p) {
    uint32_t a;
    asm("{ .reg .u64 t; cvta.to.shared.u64 t, %1; cvt.u32.u64 %0, t; }" : "=r"(a) : "l"(p));
    return a;
}
__device__ __forceinline__ uint32_t pk2(float lo, float hi) {
    uint32_t r;
    asm("cvt.rn.bf16x2.f32 %0, %1, %2;" : "=r"(r) : "f"(hi), "f"(lo));
    return r;
}
__device__ __forceinline__ void split1(float v, bf* h, bf* l) {
    bf hh = __float2bfloat16(v);
    *h = hh;
    *l = __float2bfloat16(v - __bfloat162float(hh));
}
__device__ __forceinline__ void mma16816(float* c, const uint32_t* a, uint32_t b0, uint32_t b1) {
    asm volatile("mma.sync.aligned.m16n8k16.row.col.f32.bf16.bf16.f32 "
                 "{%0,%1,%2,%3}, {%4,%5,%6,%7}, {%8,%9}, {%0,%1,%2,%3};"
                 : "+f"(c[0]), "+f"(c[1]), "+f"(c[2]), "+f"(c[3])
                 : "r"(a[0]), "r"(a[1]), "r"(a[2]), "r"(a[3]), "r"(b0), "r"(b1));
}
__device__ __forceinline__ void ldm4(uint32_t* r, uint32_t addr) {
    asm volatile("ldmatrix.sync.aligned.m8n8.x4.shared.b16 {%0,%1,%2,%3}, [%4];"
                 : "=r"(r[0]), "=r"(r[1]), "=r"(r[2]), "=r"(r[3]) : "r"(addr));
}
__device__ __forceinline__ void ldm4t(uint32_t* r, uint32_t addr) {
    asm volatile("ldmatrix.sync.aligned.m8n8.x4.trans.shared.b16 {%0,%1,%2,%3}, [%4];"
                 : "=r"(r[0]), "=r"(r[1]), "=r"(r[2]), "=r"(r[3]) : "r"(addr));
}
#define CPA(dst, src) asm volatile("cp.async.cg.shared.global [%0], [%1], 16;" :: "r"(dst), "l"(src))
#define CPC()  asm volatile("cp.async.commit_group;" ::: "memory")
#define CPW0() asm volatile("cp.async.wait_group 0;" ::: "memory")
#define CPW1() asm volatile("cp.async.wait_group 1;" ::: "memory")

// ---------------- prep kernels ----------------
__global__ void prep_wq(const float* __restrict__ wq, bf* __restrict__ oh, bf* __restrict__ ol) {
    int idx = blockIdx.x * 256 + threadIdx.x;          // 12*768*768
    int lay = idx / LAYW, r = idx % LAYW;
    int n = r / EDIM, e = r % EDIM;
    float v = wq[(size_t)lay * LAYW + (n >> 6) * (EDIM * DH) + e * DH + (n & 63)];
    split1(v, &oh[idx], &ol[idx]);
}
__global__ void split_arr(const float* __restrict__ s, bf* __restrict__ oh, bf* __restrict__ ol) {
    int idx = blockIdx.x * 256 + threadIdx.x;
    split1(s[idx], &oh[idx], &ol[idx]);
}
__global__ void add_pe_kernel(const float* __restrict__ tokens, float* __restrict__ x,
                              bf* __restrict__ xh, bf* __restrict__ xl) {
    int idx = blockIdx.x * 256 + threadIdx.x;
    int e = idx % EDIM, n = idx / EDIM, s = n & 511;
    float p = (e < 384) ? 10000.0f : 10001.0f;
    float ang = (float)s / p;
    float pe = (e & 1) ? cosf(ang) : sinf(ang);
    float v = tokens[idx] + pe;
    x[idx] = v;
    split1(v, &xh[idx], &xl[idx]);
}

// ---------------- bf16-split GEMM: D[M,N] = A[M,K]*B[N,K]^T ----------------
// 128x128 CTA tile, 8 warps (4x2), warp 32x64, K chunk 64, double-buffered cp.async.
// (R7 configuration — measured best.)
#define GP 72
#define ABUF (128 * GP)
#define BUFSZ (4 * ABUF)
#define GEMM_SMEM (2 * BUFSZ * 2)        // 147456 bytes

__device__ __forceinline__ void gemm_load(uint32_t sb, int b, const bf* Ah, const bf* Al,
                                          const bf* Bh, const bf* Bl,
                                          int bm, int bn, int K, int k0, int tid) {
    uint32_t base = sb + (uint32_t)(b * BUFSZ) * 2;
#pragma unroll
    for (int m = 0; m < 4; m++) {
        int task = tid + 256 * m;
        int r = task >> 3, gc = (task & 7) * 8;
        uint32_t so = (uint32_t)(r * GP + gc) * 2;
        size_t ga = (size_t)(bm + r) * K + k0 + gc;
        size_t gb = (size_t)(bn + r) * K + k0 + gc;
        CPA(base + so,             Ah + ga);
        CPA(base + ABUF * 2 + so,  Al + ga);
        CPA(base + ABUF * 4 + so,  Bh + gb);
        CPA(base + ABUF * 6 + so,  Bl + gb);
    }
    CPC();
}

template <bool OUTSPLIT>
__global__ void __launch_bounds__(256, 1)
gemm_bf(const bf* __restrict__ Ah, const bf* __restrict__ Al,
        const bf* __restrict__ Bh, const bf* __restrict__ Bl,
        float* __restrict__ C, bf* __restrict__ Ch, bf* __restrict__ Cl,
        int M, int N, int K) {
    extern __shared__ bf ds[];
    uint32_t sb = smem_u32(ds);
    int tid = threadIdx.x, wid = tid >> 5;
    int bm = blockIdx.y * 128, bn = blockIdx.x * 128;
    int wm = (wid >> 1) * 32, wn = (wid & 1) * 64;

    wmma::fragment<wmma::accumulator, 16, 16, 16, float> acc[2][4];
#pragma unroll
    for (int i = 0; i < 2; i++)
#pragma unroll
        for (int j = 0; j < 4; j++) wmma::fill_fragment(acc[i][j], 0.f);

    const int NCH = K / 64;                      // 12
    gemm_load(sb, 0, Ah, Al, Bh, Bl, bm, bn, K, 0, tid);

    for (int c = 0; c < NCH; c++) {
        if (c + 1 < NCH) {
            gemm_load(sb, (c + 1) & 1, Ah, Al, Bh, Bl, bm, bn, K, (c + 1) * 64, tid);
            CPW1();
        } else {
            CPW0();
        }
        __syncthreads();
        bf* Ahs = ds + (size_t)(c & 1) * BUFSZ;
        bf* Als = Ahs + ABUF;
        bf* Bhs = Ahs + 2 * ABUF;
        bf* Bls = Ahs + 3 * ABUF;
#pragma unroll
        for (int kc = 0; kc < 4; kc++) {
            wmma::fragment<wmma::matrix_a, 16, 16, 16, bf, wmma::row_major> ah2[2], al2[2];
#pragma unroll
            for (int i = 0; i < 2; i++) {
                wmma::load_matrix_sync(ah2[i], &Ahs[(wm + 16 * i) * GP + kc * 16], GP);
                wmma::load_matrix_sync(al2[i], &Als[(wm + 16 * i) * GP + kc * 16], GP);
            }
#pragma unroll
            for (int j = 0; j < 4; j++) {
                wmma::fragment<wmma::matrix_b, 16, 16, 16, bf, wmma::col_major> bh2, bl2;
                wmma::load_matrix_sync(bh2, &Bhs[(wn + 16 * j) * GP + kc * 16], GP);
                wmma::load_matrix_sync(bl2, &Bls[(wn + 16 * j) * GP + kc * 16], GP);
#pragma unroll
                for (int i = 0; i < 2; i++) {
                    wmma::mma_sync(acc[i][j], ah2[i], bh2, acc[i][j]);
                    wmma::mma_sync(acc[i][j], ah2[i], bl2, acc[i][j]);
                    wmma::mma_sync(acc[i][j], al2[i], bh2, acc[i][j]);
                }
            }
        }
        __syncthreads();
    }

    if (!OUTSPLIT) {
#pragma unroll
        for (int i = 0; i < 2; i++)
#pragma unroll
            for (int j = 0; j < 4; j++)
                wmma::store_matrix_sync(&C[(size_t)(bm + wm + 16 * i) * N + bn + wn + 16 * j],
                                        acc[i][j], N, wmma::mem_row_major);
    } else {
        float* cs = (float*)ds;                   // 128x128 fp32 staging (64KB)
#pragma unroll
        for (int i = 0; i < 2; i++)
#pragma unroll
            for (int j = 0; j < 4; j++)
                wmma::store_matrix_sync(&cs[(wm + 16 * i) * 128 + wn + 16 * j],
                                        acc[i][j], 128, wmma::mem_row_major);
        __syncthreads();
#pragma unroll
        for (int m = 0; m < 64; m++) {
            int idx = tid + 256 * m;
            int r = idx >> 7, cc = idx & 127;
            size_t go = (size_t)(bm + r) * N + bn + cc;
            split1(cs[r * 128 + cc], &Ch[go], &Cl[go]);
        }
    }
}

// ---------------- flash attention (q==k==v), pre-split bf16, cp.async pipeline ----------------
// Epilogue writes the TRANSPOSED split output zth/ztl [2048 x 768] directly:
// this CTA (h, rb) owns zcT columns h*64+2rb and h*64+2rb+1 across all 2048 rows.
#define FP 72
#define FQH 0
#define FQL (64 * FP)
#define FKH(b) (2 * 64 * FP + (b) * 2 * 64 * FP)
#define FKL(b) (FKH(b) + 64 * FP)
#define FLASH_SMEM (6 * 64 * FP * 2)

__global__ void __launch_bounds__(128, 3)
flash_bf(const bf* __restrict__ Qh, const bf* __restrict__ Ql,
         bf* __restrict__ zth, bf* __restrict__ ztl) {
    extern __shared__ bf ds[];
    uint32_t sb = smem_u32(ds);
    int tid = threadIdx.x, lane = tid & 31, wid = tid >> 5;
    int h = blockIdx.y, rb = blockIdx.x;
    size_t hoff = (size_t)h * DH;

#pragma unroll
    for (int m = 0; m < 4; m++) {
        int task = tid + 128 * m;
        int r = task >> 3, gc = (task & 7) * 8;
        size_t go = (size_t)(rb * 64 + r) * EDIM + hoff + gc;
        CPA(sb + (FQH + r * FP + gc) * 2, Qh + go);
        CPA(sb + (FQL + r * FP + gc) * 2, Ql + go);
        size_t gk = (size_t)r * EDIM + hoff + gc;
        CPA(sb + (FKH(0) + r * FP + gc) * 2, Qh + gk);
        CPA(sb + (FKL(0) + r * FP + gc) * 2, Ql + gk);
    }
    CPC(); CPW0();
    __syncthreads();

    int ar = wid * 16 + (lane >> 2);
    int ac = 2 * (lane & 3);
    uint32_t qah[4][4], qal[4][4];
#pragma unroll
    for (int kc = 0; kc < 4; kc++) {
        int cb = kc * 16 + ac;
        qah[kc][0] = *(uint32_t*)&ds[FQH + (ar)     * FP + cb];
        qah[kc][1] = *(uint32_t*)&ds[FQH + (ar + 8) * FP + cb];
        qah[kc][2] = *(uint32_t*)&ds[FQH + (ar)     * FP + cb + 8];
        qah[kc][3] = *(uint32_t*)&ds[FQH + (ar + 8) * FP + cb + 8];
        qal[kc][0] = *(uint32_t*)&ds[FQL + (ar)     * FP + cb];
        qal[kc][1] = *(uint32_t*)&ds[FQL + (ar + 8) * FP + cb];
        qal[kc][2] = *(uint32_t*)&ds[FQL + (ar)     * FP + cb + 8];
        qal[kc][3] = *(uint32_t*)&ds[FQL + (ar + 8) * FP + cb + 8];
    }

    float m0 = -1e30f, m1 = -1e30f, l0 = 0.f, l1 = 0.f;
    float o[8][4];
#pragma unroll
    for (int j = 0; j < 8; j++)
#pragma unroll
        for (int c = 0; c < 4; c++) o[j][c] = 0.f;

    int g = lane >> 3, i8 = lane & 7;
    uint32_t offS = (uint32_t)(((g >> 1) * 8 + i8) * FP + (g & 1) * 8) * 2;
    uint32_t offV = (uint32_t)(((g & 1) * 8 + i8) * FP + (g >> 1) * 8) * 2;

    for (int ct = 0; ct < 32; ct++) {
        if (ct < 31) {
            int b = (ct + 1) & 1;
#pragma unroll
            for (int m = 0; m < 4; m++) {
                int task = tid + 128 * m;
                int r = task >> 3, gc = (task & 7) * 8;
                size_t gk = (size_t)((ct + 1) * 64 + r) * EDIM + hoff + gc;
                CPA(sb + (FKH(b) + r * FP + gc) * 2, Qh + gk);
                CPA(sb + (FKL(b) + r * FP + gc) * 2, Ql + gk);
            }
            CPC(); CPW1();
        } else {
            CPW0();
        }
        __syncthreads();
        uint32_t khb = sb + FKH(ct & 1) * 2, klb = sb + FKL(ct & 1) * 2;

        float sacc[8][4];
#pragma unroll
        for (int j = 0; j < 8; j++)
#pragma unroll
            for (int c = 0; c < 4; c++) sacc[j][c] = 0.f;
#pragma unroll
        for (int kc = 0; kc < 4; kc++) {
#pragma unroll
            for (int jp = 0; jp < 4; jp++) {
                uint32_t toff = (uint32_t)(jp * 16 * FP + kc * 16) * 2;
                uint32_t bh[4], bl[4];
                ldm4(bh, khb + offS + toff);
                ldm4(bl, klb + offS + toff);
                mma16816(sacc[2 * jp],     qah[kc], bh[0], bh[1]);
                mma16816(sacc[2 * jp],     qah[kc], bl[0], bl[1]);
                mma16816(sacc[2 * jp],     qal[kc], bh[0], bh[1]);
                mma16816(sacc[2 * jp + 1], qah[kc], bh[2], bh[3]);
                mma16816(sacc[2 * jp + 1], qah[kc], bl[2], bl[3]);
                mma16816(sacc[2 * jp + 1], qal[kc], bh[2], bh[3]);
            }
        }

        float mx0 = -1e30f, mx1 = -1e30f;
#pragma unroll
        for (int j = 0; j < 8; j++) {
#pragma unroll
            for (int c = 0; c < 4; c++) sacc[j][c] *= 0.125f;
            mx0 = fmaxf(mx0, fmaxf(sacc[j][0], sacc[j][1]));
            mx1 = fmaxf(mx1, fmaxf(sacc[j][2], sacc[j][3]));
        }
        mx0 = fmaxf(mx0, __shfl_xor_sync(0xffffffffu, mx0, 1));
        mx0 = fmaxf(mx0, __shfl_xor_sync(0xffffffffu, mx0, 2));
        mx1 = fmaxf(mx1, __shfl_xor_sync(0xffffffffu, mx1, 1));
        mx1 = fmaxf(mx1, __shfl_xor_sync(0xffffffffu, mx1, 2));
        float mn0 = fmaxf(m0, mx0), mn1 = fmaxf(m1, mx1);
        float al0 = __expf(m0 - mn0), al1 = __expf(m1 - mn1);

        float rs0 = 0.f, rs1 = 0.f;
        uint32_t pah[4][4], pal[4][4];
#pragma unroll
        for (int j = 0; j < 8; j++) {
            float p0 = __expf(sacc[j][0] - mn0);
            float p1 = __expf(sacc[j][1] - mn0);
            float p2 = __expf(sacc[j][2] - mn1);
            float p3 = __expf(sacc[j][3] - mn1);
            rs0 += p0 + p1; rs1 += p2 + p3;
            float f0 = __bfloat162float(__float2bfloat16(p0));
            float f1 = __bfloat162float(__float2bfloat16(p1));
            float f2 = __bfloat162float(__float2bfloat16(p2));
            float f3 = __bfloat162float(__float2bfloat16(p3));
            int kc = j >> 1, off = (j & 1) * 2;
            pah[kc][off]     = pk2(p0, p1);
            pah[kc][off + 1] = pk2(p2, p3);
            pal[kc][off]     = pk2(p0 - f0, p1 - f1);
            pal[kc][off + 1] = pk2(p2 - f2, p3 - f3);
        }
        rs0 += __shfl_xor_sync(0xffffffffu, rs0, 1);
        rs0 += __shfl_xor_sync(0xffffffffu, rs0, 2);
        rs1 += __shfl_xor_sync(0xffffffffu, rs1, 1);
        rs1 += __shfl_xor_sync(0xffffffffu, rs1, 2);
        l0 = l0 * al0 + rs0;
        l1 = l1 * al1 + rs1;
        m0 = mn0; m1 = mn1;
#pragma unroll
        for (int j = 0; j < 8; j++) {
            o[j][0] *= al0; o[j][1] *= al0;
            o[j][2] *= al1; o[j][3] *= al1;
        }

#pragma unroll
        for (int kc = 0; kc < 4; kc++) {
#pragma unroll
            for (int jdp = 0; jdp < 4; jdp++) {
                uint32_t toff = (uint32_t)(kc * 16 * FP + jdp * 16) * 2;
                uint32_t vh[4], vl[4];
                ldm4t(vh, khb + offV + toff);
                ldm4t(vl, klb + offV + toff);
                mma16816(o[2 * jdp],     pah[kc], vh[0], vh[1]);
                mma16816(o[2 * jdp],     pah[kc], vl[0], vl[1]);
                mma16816(o[2 * jdp],     pal[kc], vh[0], vh[1]);
                mma16816(o[2 * jdp + 1], pah[kc], vh[2], vh[3]);
                mma16816(o[2 * jdp + 1], pah[kc], vl[2], vl[3]);
                mma16816(o[2 * jdp + 1], pal[kc], vh[2], vh[3]);
            }
        }
        __syncthreads();
    }

    // ---- epilogue: stage O (scaled) in smem, then write transposed split output ----
    const int SOP = 68;                              // fp32 staging pitch
    float* sO = (float*)ds;                          // 64x68 fp32 = 17.4KB (Q region)
    float inv0 = 1.f / l0, inv1 = 1.f / l1;
#pragma unroll
    for (int jd = 0; jd < 8; jd++) {
        int d = jd * 8 + ac;
        sO[ar * SOP + d]           = o[jd][0] * inv0;
        sO[ar * SOP + d + 1]       = o[jd][1] * inv0;
        sO[(ar + 8) * SOP + d]     = o[jd][2] * inv1;
        sO[(ar + 8) * SOP + d + 1] = o[jd][3] * inv1;
    }
    __syncthreads();
    int cb = h * 64 + 2 * rb;                        // two adjacent zcT columns
#pragma unroll
    for (int m = 0; m < 16; m++) {
        int r2 = tid + 128 * m;                      // 0..2047: zcT row = (n&31)*64 + d
        int j = r2 >> 6, d = r2 & 63;
        float vlo = sO[j * SOP + d];                 // token group n>>5 == 2*rb
        float vhi = sO[(j + 32) * SOP + d];          // token group n>>5 == 2*rb+1
        bf h0 = __float2bfloat16(vlo), h1 = __float2bfloat16(vhi);
        float r0 = vlo - __bfloat162float(h0), r1 = vhi - __bfloat162float(h1);
        uint32_t ph = ((uint32_t)*(uint16_t*)&h1 << 16) | *(uint16_t*)&h0;
        bf e0 = __float2bfloat16(r0), e1 = __float2bfloat16(r1);
        uint32_t pl = ((uint32_t)*(uint16_t*)&e1 << 16) | *(uint16_t*)&e0;
        size_t go = (size_t)r2 * EDIM + cb;
        *(uint32_t*)&zth[go] = ph;
        *(uint32_t*)&ztl[go] = pl;
    }
}

// ---------------- fused residual (+bias) + LayerNorm (+optional split out) ----------------
template <bool SPLIT>
__global__ void add_ln(const float* __restrict__ A, const float* __restrict__ Bd,
                       const float* __restrict__ g, const float* __restrict__ bb,
                       const float* __restrict__ extra, float* __restrict__ out,
                       bf* __restrict__ oh, bf* __restrict__ ol) {
    __shared__ float red[8];
    int n = blockIdx.x, tid = threadIdx.x;
    float loc[3];
    float s = 0.f;
#pragma unroll
    for (int i = 0; i < 3; i++) {
        int e = tid + i * 256;
        float v = A[(size_t)n * EDIM + e] + Bd[(size_t)n * EDIM + e];
        if (extra) v += extra[e];
        loc[i] = v; s += v;
    }
#pragma unroll
    for (int o = 16; o; o >>= 1) s += __shfl_xor_sync(0xffffffffu, s, o);
    if ((tid & 31) == 0) red[tid >> 5] = s;
    __syncthreads();
    if (tid < 32) {
        float t = (tid < 8) ? red[tid] : 0.f;
#pragma unroll
        for (int o = 4; o; o >>= 1) t += __shfl_xor_sync(0xffffffffu, t, o);
        if (tid == 0) red[0] = t;
    }
    __syncthreads();
    float mu = red[0] * (1.f / 768.f);
    __syncthreads();
    float sq = 0.f;
#pragma unroll
    for (int i = 0; i < 3; i++) { float d = loc[i] - mu; sq += d * d; }
#pragma unroll
    for (int o = 16; o; o >>= 1) sq += __shfl_xor_sync(0xffffffffu, sq, o);
    if ((tid & 31) == 0) red[tid >> 5] = sq;
    __syncthreads();
    if (tid < 32) {
        float t = (tid < 8) ? red[tid] : 0.f;
#pragma unroll
        for (int o = 4; o; o >>= 1) t += __shfl_xor_sync(0xffffffffu, t, o);
        if (tid == 0) red[0] = t;
    }
    __syncthreads();
    float var = red[0] * (1.f / 768.f);
    float inv = rsqrtf(var + 1e-5f);
#pragma unroll
    for (int i = 0; i < 3; i++) {
        int e = tid + i * 256;
        float v = (loc[i] - mu) * inv * g[e] + bb[e];
        size_t go = (size_t)n * EDIM + e;
        out[go] = v;
        if (SPLIT) split1(v, &oh[go], &ol[go]);
    }
}

// ---------------- launch ----------------
extern "C" void kernel_launch(void* const* d_in, const int* in_sizes, int n_in,
                              void* d_out, int out_size) {
    const float* tokens = (const float*)d_in[0];
    const float* wq = (const float*)d_in[1];
    const float* wo = (const float*)d_in[2];
    const float* g1 = (const float*)d_in[3];
    const float* b1 = (const float*)d_in[4];
    const float* fw = (const float*)d_in[5];
    const float* fb = (const float*)d_in[6];
    const float* g2 = (const float*)d_in[7];
    const float* b2 = (const float*)d_in[8];
    float* out = (float*)d_out;

    float *x, *mh, *l1, *ffn;
    bf *xh, *xl, *qh, *ql, *l1h, *l1l, *zth, *ztl;
    bf *wqh, *wql, *woh, *wol, *fwh, *fwl;
    cudaGetSymbolAddress((void**)&x, g_x);     cudaGetSymbolAddress((void**)&mh, g_mh);
    cudaGetSymbolAddress((void**)&l1, g_l1);   cudaGetSymbolAddress((void**)&ffn, g_ffn);
    cudaGetSymbolAddress((void**)&xh, g_xh);   cudaGetSymbolAddress((void**)&xl, g_xl);
    cudaGetSymbolAddress((void**)&qh, g_qh);   cudaGetSymbolAddress((void**)&ql, g_ql);
    cudaGetSymbolAddress((void**)&l1h, g_l1h); cudaGetSymbolAddress((void**)&l1l, g_l1l);
    cudaGetSymbolAddress((void**)&zth, g_zth); cudaGetSymbolAddress((void**)&ztl, g_ztl);
    cudaGetSymbolAddress((void**)&wqh, g_wqh); cudaGetSymbolAddress((void**)&wql, g_wql);
    cudaGetSymbolAddress((void**)&woh, g_woh); cudaGetSymbolAddress((void**)&wol, g_wol);
    cudaGetSymbolAddress((void**)&fwh, g_fwh); cudaGetSymbolAddress((void**)&fwl, g_fwl);

    cudaFuncSetAttribute(gemm_bf<false>, cudaFuncAttributeMaxDynamicSharedMemorySize, GEMM_SMEM);
    cudaFuncSetAttribute(gemm_bf<true>,  cudaFuncAttributeMaxDynamicSharedMemorySize, GEMM_SMEM);
    cudaFuncSetAttribute(flash_bf, cudaFuncAttributeMaxDynamicSharedMemorySize, FLASH_SMEM);

    prep_wq<<<12 * LAYW / 256, 256>>>(wq, wqh, wql);
    split_arr<<<12 * LAYW / 256, 256>>>(wo, woh, wol);
    split_arr<<<12 * LAYW / 256, 256>>>(fw, fwh, fwl);
    add_pe_kernel<<<(N_TOK * EDIM) / 256, 256>>>(tokens, x, xh, xl);

    for (int step = 0; step < 13; step++) {
        int lidx = (step == 0) ? 0 : step - 1;
        const bf* wqh_l = wqh + (size_t)lidx * LAYW;
        const bf* wql_l = wql + (size_t)lidx * LAYW;
        const bf* woh_l = woh + (size_t)lidx * LAYW;
        const bf* wol_l = wol + (size_t)lidx * LAYW;
        const bf* fwh_l = fwh + (size_t)lidx * LAYW;
        const bf* fwl_l = fwl + (size_t)lidx * LAYW;

        // q = x @ wqfT^T -> split bf16 output directly   [2048x768], 128x128 tiles
        gemm_bf<true><<<dim3(EDIM / 128, N_TOK / 128), 256, GEMM_SMEM>>>(
            xh, xl, wqh_l, wql_l, nullptr, qh, ql, N_TOK, EDIM, EDIM);

        // attention -> zth/ztl (transposed split output written directly)
        flash_bf<<<dim3(32, HEADS), 128, FLASH_SMEM>>>(qh, ql, zth, ztl);

        // mh = wo @ zcT^T   [768x2048]
        gemm_bf<false><<<dim3(N_TOK / 128, EDIM / 128), 256, GEMM_SMEM>>>(
            woh_l, wol_l, zth, ztl, mh, nullptr, nullptr, EDIM, N_TOK, EDIM);

        add_ln<true><<<N_TOK, 256>>>(x, mh, g1 + lidx * EDIM, b1 + lidx * EDIM,
                                     nullptr, l1, l1h, l1l);

        // ffn = l1 @ fw^T (bias folded into next add_ln)   [2048x768]
        gemm_bf<false><<<dim3(EDIM / 128, N_TOK / 128), 256, GEMM_SMEM>>>(
            l1h, l1l, fwh_l, fwl_l, ffn, nullptr, nullptr, N_TOK, EDIM, EDIM);

        if (step == 12)
            add_ln<false><<<N_TOK, 256>>>(l1, ffn, g2 + lidx * EDIM, b2 + lidx * EDIM,
                                          fb + lidx * EDIM, out, nullptr, nullptr);
        else
            add_ln<true><<<N_TOK, 256>>>(l1, ffn, g2 + lidx * EDIM, b2 + lidx * EDIM,
                                         fb + lidx * EDIM, x, xh, xl);
    }
}

// round 10
// speedup vs baseline: 1.0603x; 1.0356x over previous
#include <cuda_runtime.h>
#include <cuda_bf16.h>
#include <mma.h>
#include <cstdint>
using namespace nvcuda;
typedef __nv_bfloat16 bf;

#define N_TOK 2048
#define EDIM  768
#define HEADS 12
#define DH    64
#define LAYW  (EDIM * EDIM)

// fp32 scratch
__device__ float g_x[N_TOK * EDIM], g_mh[EDIM * N_TOK], g_l1[N_TOK * EDIM], g_ffn[N_TOK * EDIM];
// bf16 split activations
__device__ bf g_xh[N_TOK * EDIM], g_xl[N_TOK * EDIM], g_qh[N_TOK * EDIM], g_ql[N_TOK * EDIM],
              g_l1h[N_TOK * EDIM], g_l1l[N_TOK * EDIM], g_zch[EDIM * N_TOK], g_zcl[EDIM * N_TOK];
// bf16 split weights, all 12 layers
__device__ bf g_wqh[12 * LAYW], g_wql[12 * LAYW], g_woh[12 * LAYW], g_wol[12 * LAYW],
              g_fwh[12 * LAYW], g_fwl[12 * LAYW];

// ---------------- helpers ----------------
__device__ __forceinline__ uint32_t smem_u32(const void* p) {
    uint32_t a;
    asm("{ .reg .u64 t; cvta.to.shared.u64 t, %1; cvt.u32.u64 %0, t; }" : "=r"(a) : "l"(p));
    return a;
}
__device__ __forceinline__ uint32_t pk2(float lo, float hi) {
    uint32_t r;
    asm("cvt.rn.bf16x2.f32 %0, %1, %2;" : "=r"(r) : "f"(hi), "f"(lo));
    return r;
}
__device__ __forceinline__ void split1(float v, bf* h, bf* l) {
    bf hh = __float2bfloat16(v);
    *h = hh;
    *l = __float2bfloat16(v - __bfloat162float(hh));
}
__device__ __forceinline__ void mma16816(float* c, const uint32_t* a, uint32_t b0, uint32_t b1) {
    asm volatile("mma.sync.aligned.m16n8k16.row.col.f32.bf16.bf16.f32 "
                 "{%0,%1,%2,%3}, {%4,%5,%6,%7}, {%8,%9}, {%0,%1,%2,%3};"
                 : "+f"(c[0]), "+f"(c[1]), "+f"(c[2]), "+f"(c[3])
                 : "r"(a[0]), "r"(a[1]), "r"(a[2]), "r"(a[3]), "r"(b0), "r"(b1));
}
__device__ __forceinline__ void ldm4(uint32_t* r, uint32_t addr) {
    asm volatile("ldmatrix.sync.aligned.m8n8.x4.shared.b16 {%0,%1,%2,%3}, [%4];"
                 : "=r"(r[0]), "=r"(r[1]), "=r"(r[2]), "=r"(r[3]) : "r"(addr));
}
__device__ __forceinline__ void ldm4t(uint32_t* r, uint32_t addr) {
    asm volatile("ldmatrix.sync.aligned.m8n8.x4.trans.shared.b16 {%0,%1,%2,%3}, [%4];"
                 : "=r"(r[0]), "=r"(r[1]), "=r"(r[2]), "=r"(r[3]) : "r"(addr));
}
#define CPA(dst, src) asm volatile("cp.async.cg.shared.global [%0], [%1], 16;" :: "r"(dst), "l"(src))
#define CPC()  asm volatile("cp.async.commit_group;" ::: "memory")
#define CPW0() asm volatile("cp.async.wait_group 0;" ::: "memory")
#define CPW1() asm volatile("cp.async.wait_group 1;" ::: "memory")

// ---------------- prep kernels ----------------
__global__ void prep_wq(const float* __restrict__ wq, bf* __restrict__ oh, bf* __restrict__ ol) {
    int idx = blockIdx.x * 256 + threadIdx.x;          // 12*768*768
    int lay = idx / LAYW, r = idx % LAYW;
    int n = r / EDIM, e = r % EDIM;
    float v = wq[(size_t)lay * LAYW + (n >> 6) * (EDIM * DH) + e * DH + (n & 63)];
    split1(v, &oh[idx], &ol[idx]);
}
__global__ void split_arr(const float* __restrict__ s, bf* __restrict__ oh, bf* __restrict__ ol) {
    int idx = blockIdx.x * 256 + threadIdx.x;
    split1(s[idx], &oh[idx], &ol[idx]);
}
__global__ void add_pe_kernel(const float* __restrict__ tokens, float* __restrict__ x,
                              bf* __restrict__ xh, bf* __restrict__ xl) {
    int idx = blockIdx.x * 256 + threadIdx.x;
    int e = idx % EDIM, n = idx / EDIM, s = n & 511;
    float p = (e < 384) ? 10000.0f : 10001.0f;
    float ang = (float)s / p;
    float pe = (e & 1) ? cosf(ang) : sinf(ang);
    float v = tokens[idx] + pe;
    x[idx] = v;
    split1(v, &xh[idx], &xl[idx]);
}

// ---------------- bf16-split GEMM ----------------
// BMODE 0 (NT): D[M,N] = A[M,K] * B[N,K]^T   (B row-major [N,K])
// BMODE 1 (NN): D[M,N] = A[M,K] * B[K,N]     (B row-major [K,N] -- zc layout)
// 128x128 CTA tile, 8 warps (4x2), warp 32x64, K chunk 64, double-buffered cp.async.
#define GP 72
#define BPN 136                            // NN-mode B pitch (64 rows x 128 cols, 8 pad)
#define ABUFE (128 * GP)                   // 9216 elems
template <int BMODE> struct GCfg {
    static const int BBUFE = (BMODE ? 64 * BPN : 128 * GP);
    static const int STAGE = 2 * ABUFE + 2 * BBUFE;
};
#define GEMM_SMEM_MAX (2 * (2 * ABUFE + 2 * ABUFE) * 2)   // NT is larger: 147456

template <int BMODE>
__device__ __forceinline__ void gemm_load(uint32_t sb, int b, const bf* Ah, const bf* Al,
                                          const bf* Bh, const bf* Bl,
                                          int bm, int bn, int N, int K, int k0, int tid) {
    const int STAGE = GCfg<BMODE>::STAGE;
    const int BBUFE = GCfg<BMODE>::BBUFE;
    uint32_t base = sb + (uint32_t)(b * STAGE) * 2;
#pragma unroll
    for (int m = 0; m < 4; m++) {          // A: 128 rows x 8 segs
        int task = tid + 256 * m;
        int r = task >> 3, gc = (task & 7) * 8;
        uint32_t so = (uint32_t)(r * GP + gc) * 2;
        size_t ga = (size_t)(bm + r) * K + k0 + gc;
        CPA(base + so,             Ah + ga);
        CPA(base + ABUFE * 2 + so, Al + ga);
    }
    if (BMODE == 0) {
#pragma unroll
        for (int m = 0; m < 4; m++) {      // B: 128 rows x 8 segs (rows = N)
            int task = tid + 256 * m;
            int r = task >> 3, gc = (task & 7) * 8;
            uint32_t so = (uint32_t)(r * GP + gc) * 2;
            size_t gb = (size_t)(bn + r) * K + k0 + gc;
            CPA(base + ABUFE * 4 + so,              Bh + gb);
            CPA(base + (ABUFE * 4 + BBUFE * 2) + so, Bl + gb);
        }
    } else {
#pragma unroll
        for (int m = 0; m < 4; m++) {      // B: 64 K-rows x 16 segs (cols = N)
            int task = tid + 256 * m;
            int r = task >> 4, gc = (task & 15) * 8;
            uint32_t so = (uint32_t)(r * BPN + gc) * 2;
            size_t gb = (size_t)(k0 + r) * N + bn + gc;
            CPA(base + ABUFE * 4 + so,              Bh + gb);
            CPA(base + (ABUFE * 4 + BBUFE * 2) + so, Bl + gb);
        }
    }
    CPC();
}

template <int BMODE, bool OUTSPLIT>
__global__ void __launch_bounds__(256, 1)
gemm_bf(const bf* __restrict__ Ah, const bf* __restrict__ Al,
        const bf* __restrict__ Bh, const bf* __restrict__ Bl,
        float* __restrict__ C, bf* __restrict__ Ch, bf* __restrict__ Cl,
        int M, int N, int K) {
    const int STAGE = GCfg<BMODE>::STAGE;
    const int BBUFE = GCfg<BMODE>::BBUFE;
    extern __shared__ bf ds[];
    uint32_t sb = smem_u32(ds);
    int tid = threadIdx.x, wid = tid >> 5;
    int bm = blockIdx.y * 128, bn = blockIdx.x * 128;
    int wm = (wid >> 1) * 32, wn = (wid & 1) * 64;

    wmma::fragment<wmma::accumulator, 16, 16, 16, float> acc[2][4];
#pragma unroll
    for (int i = 0; i < 2; i++)
#pragma unroll
        for (int j = 0; j < 4; j++) wmma::fill_fragment(acc[i][j], 0.f);

    const int NCH = K / 64;                      // 12
    gemm_load<BMODE>(sb, 0, Ah, Al, Bh, Bl, bm, bn, N, K, 0, tid);

    for (int c = 0; c < NCH; c++) {
        if (c + 1 < NCH) {
            gemm_load<BMODE>(sb, (c + 1) & 1, Ah, Al, Bh, Bl, bm, bn, N, K, (c + 1) * 64, tid);
            CPW1();
        } else {
            CPW0();
        }
        __syncthreads();
        bf* Ahs = ds + (size_t)(c & 1) * STAGE;
        bf* Als = Ahs + ABUFE;
        bf* Bhs = Ahs + 2 * ABUFE;
        bf* Bls = Bhs + BBUFE;
#pragma unroll
        for (int kc = 0; kc < 4; kc++) {
            wmma::fragment<wmma::matrix_a, 16, 16, 16, bf, wmma::row_major> ah2[2], al2[2];
#pragma unroll
            for (int i = 0; i < 2; i++) {
                wmma::load_matrix_sync(ah2[i], &Ahs[(wm + 16 * i) * GP + kc * 16], GP);
                wmma::load_matrix_sync(al2[i], &Als[(wm + 16 * i) * GP + kc * 16], GP);
            }
#pragma unroll
            for (int j = 0; j < 4; j++) {
                if (BMODE == 0) {
                    wmma::fragment<wmma::matrix_b, 16, 16, 16, bf, wmma::col_major> bh2, bl2;
                    wmma::load_matrix_sync(bh2, &Bhs[(wn + 16 * j) * GP + kc * 16], GP);
                    wmma::load_matrix_sync(bl2, &Bls[(wn + 16 * j) * GP + kc * 16], GP);
#pragma unroll
                    for (int i = 0; i < 2; i++) {
                        wmma::mma_sync(acc[i][j], ah2[i], bh2, acc[i][j]);
                        wmma::mma_sync(acc[i][j], ah2[i], bl2, acc[i][j]);
                        wmma::mma_sync(acc[i][j], al2[i], bh2, acc[i][j]);
                    }
                } else {
                    wmma::fragment<wmma::matrix_b, 16, 16, 16, bf, wmma::row_major> bh2, bl2;
                    wmma::load_matrix_sync(bh2, &Bhs[(kc * 16) * BPN + wn + 16 * j], BPN);
                    wmma::load_matrix_sync(bl2, &Bls[(kc * 16) * BPN + wn + 16 * j], BPN);
#pragma unroll
                    for (int i = 0; i < 2; i++) {
                        wmma::mma_sync(acc[i][j], ah2[i], bh2, acc[i][j]);
                        wmma::mma_sync(acc[i][j], ah2[i], bl2, acc[i][j]);
                        wmma::mma_sync(acc[i][j], al2[i], bh2, acc[i][j]);
                    }
                }
            }
        }
        __syncthreads();
    }

    if (!OUTSPLIT) {
#pragma unroll
        for (int i = 0; i < 2; i++)
#pragma unroll
            for (int j = 0; j < 4; j++)
                wmma::store_matrix_sync(&C[(size_t)(bm + wm + 16 * i) * N + bn + wn + 16 * j],
                                        acc[i][j], N, wmma::mem_row_major);
    } else {
        float* cs = (float*)ds;                   // 128x128 fp32 staging
#pragma unroll
        for (int i = 0; i < 2; i++)
#pragma unroll
            for (int j = 0; j < 4; j++)
                wmma::store_matrix_sync(&cs[(wm + 16 * i) * 128 + wn + 16 * j],
                                        acc[i][j], 128, wmma::mem_row_major);
        __syncthreads();
#pragma unroll
        for (int m = 0; m < 64; m++) {
            int idx = tid + 256 * m;
            int r = idx >> 7, cc = idx & 127;
            size_t go = (size_t)(bm + r) * N + bn + cc;
            split1(cs[r * 128 + cc], &Ch[go], &Cl[go]);
        }
    }
}

// ---------------- flash attention (q==k==v), pre-split bf16, cp.async pipeline ----------------
// Epilogue writes SPLIT bf16 zc in its natural layout (coalesced, same addresses as fp32 zc):
// zc[(h*64 + n/32)*2048 + (n%32)*64 + d]
#define FP 72
#define FQH 0
#define FQL (64 * FP)
#define FKH(b) (2 * 64 * FP + (b) * 2 * 64 * FP)
#define FKL(b) (FKH(b) + 64 * FP)
#define FLASH_SMEM (6 * 64 * FP * 2)

__global__ void __launch_bounds__(128, 3)
flash_bf(const bf* __restrict__ Qh, const bf* __restrict__ Ql,
         bf* __restrict__ zch, bf* __restrict__ zcl) {
    extern __shared__ bf ds[];
    uint32_t sb = smem_u32(ds);
    int tid = threadIdx.x, lane = tid & 31, wid = tid >> 5;
    int h = blockIdx.y, rb = blockIdx.x;
    size_t hoff = (size_t)h * DH;

#pragma unroll
    for (int m = 0; m < 4; m++) {
        int task = tid + 128 * m;
        int r = task >> 3, gc = (task & 7) * 8;
        size_t go = (size_t)(rb * 64 + r) * EDIM + hoff + gc;
        CPA(sb + (FQH + r * FP + gc) * 2, Qh + go);
        CPA(sb + (FQL + r * FP + gc) * 2, Ql + go);
        size_t gk = (size_t)r * EDIM + hoff + gc;
        CPA(sb + (FKH(0) + r * FP + gc) * 2, Qh + gk);
        CPA(sb + (FKL(0) + r * FP + gc) * 2, Ql + gk);
    }
    CPC(); CPW0();
    __syncthreads();

    int ar = wid * 16 + (lane >> 2);
    int ac = 2 * (lane & 3);
    uint32_t qah[4][4], qal[4][4];
#pragma unroll
    for (int kc = 0; kc < 4; kc++) {
        int cb = kc * 16 + ac;
        qah[kc][0] = *(uint32_t*)&ds[FQH + (ar)     * FP + cb];
        qah[kc][1] = *(uint32_t*)&ds[FQH + (ar + 8) * FP + cb];
        qah[kc][2] = *(uint32_t*)&ds[FQH + (ar)     * FP + cb + 8];
        qah[kc][3] = *(uint32_t*)&ds[FQH + (ar + 8) * FP + cb + 8];
        qal[kc][0] = *(uint32_t*)&ds[FQL + (ar)     * FP + cb];
        qal[kc][1] = *(uint32_t*)&ds[FQL + (ar + 8) * FP + cb];
        qal[kc][2] = *(uint32_t*)&ds[FQL + (ar)     * FP + cb + 8];
        qal[kc][3] = *(uint32_t*)&ds[FQL + (ar + 8) * FP + cb + 8];
    }

    float m0 = -1e30f, m1 = -1e30f, l0 = 0.f, l1 = 0.f;
    float o[8][4];
#pragma unroll
    for (int j = 0; j < 8; j++)
#pragma unroll
        for (int c = 0; c < 4; c++) o[j][c] = 0.f;

    int g = lane >> 3, i8 = lane & 7;
    uint32_t offS = (uint32_t)(((g >> 1) * 8 + i8) * FP + (g & 1) * 8) * 2;
    uint32_t offV = (uint32_t)(((g & 1) * 8 + i8) * FP + (g >> 1) * 8) * 2;

    for (int ct = 0; ct < 32; ct++) {
        if (ct < 31) {
            int b = (ct + 1) & 1;
#pragma unroll
            for (int m = 0; m < 4; m++) {
                int task = tid + 128 * m;
                int r = task >> 3, gc = (task & 7) * 8;
                size_t gk = (size_t)((ct + 1) * 64 + r) * EDIM + hoff + gc;
                CPA(sb + (FKH(b) + r * FP + gc) * 2, Qh + gk);
                CPA(sb + (FKL(b) + r * FP + gc) * 2, Ql + gk);
            }
            CPC(); CPW1();
        } else {
            CPW0();
        }
        __syncthreads();
        uint32_t khb = sb + FKH(ct & 1) * 2, klb = sb + FKL(ct & 1) * 2;

        float sacc[8][4];
#pragma unroll
        for (int j = 0; j < 8; j++)
#pragma unroll
            for (int c = 0; c < 4; c++) sacc[j][c] = 0.f;
#pragma unroll
        for (int kc = 0; kc < 4; kc++) {
#pragma unroll
            for (int jp = 0; jp < 4; jp++) {
                uint32_t toff = (uint32_t)(jp * 16 * FP + kc * 16) * 2;
                uint32_t bh[4], bl[4];
                ldm4(bh, khb + offS + toff);
                ldm4(bl, klb + offS + toff);
                mma16816(sacc[2 * jp],     qah[kc], bh[0], bh[1]);
                mma16816(sacc[2 * jp],     qah[kc], bl[0], bl[1]);
                mma16816(sacc[2 * jp],     qal[kc], bh[0], bh[1]);
                mma16816(sacc[2 * jp + 1], qah[kc], bh[2], bh[3]);
                mma16816(sacc[2 * jp + 1], qah[kc], bl[2], bl[3]);
                mma16816(sacc[2 * jp + 1], qal[kc], bh[2], bh[3]);
            }
        }

        float mx0 = -1e30f, mx1 = -1e30f;
#pragma unroll
        for (int j = 0; j < 8; j++) {
#pragma unroll
            for (int c = 0; c < 4; c++) sacc[j][c] *= 0.125f;
            mx0 = fmaxf(mx0, fmaxf(sacc[j][0], sacc[j][1]));
            mx1 = fmaxf(mx1, fmaxf(sacc[j][2], sacc[j][3]));
        }
        mx0 = fmaxf(mx0, __shfl_xor_sync(0xffffffffu, mx0, 1));
        mx0 = fmaxf(mx0, __shfl_xor_sync(0xffffffffu, mx0, 2));
        mx1 = fmaxf(mx1, __shfl_xor_sync(0xffffffffu, mx1, 1));
        mx1 = fmaxf(mx1, __shfl_xor_sync(0xffffffffu, mx1, 2));
        float mn0 = fmaxf(m0, mx0), mn1 = fmaxf(m1, mx1);
        float al0 = __expf(m0 - mn0), al1 = __expf(m1 - mn1);

        float rs0 = 0.f, rs1 = 0.f;
        uint32_t pah[4][4], pal[4][4];
#pragma unroll
        for (int j = 0; j < 8; j++) {
            float p0 = __expf(sacc[j][0] - mn0);
            float p1 = __expf(sacc[j][1] - mn0);
            float p2 = __expf(sacc[j][2] - mn1);
            float p3 = __expf(sacc[j][3] - mn1);
            rs0 += p0 + p1; rs1 += p2 + p3;
            float f0 = __bfloat162float(__float2bfloat16(p0));
            float f1 = __bfloat162float(__float2bfloat16(p1));
            float f2 = __bfloat162float(__float2bfloat16(p2));
            float f3 = __bfloat162float(__float2bfloat16(p3));
            int kc = j >> 1, off = (j & 1) * 2;
            pah[kc][off]     = pk2(p0, p1);
            pah[kc][off + 1] = pk2(p2, p3);
            pal[kc][off]     = pk2(p0 - f0, p1 - f1);
            pal[kc][off + 1] = pk2(p2 - f2, p3 - f3);
        }
        rs0 += __shfl_xor_sync(0xffffffffu, rs0, 1);
        rs0 += __shfl_xor_sync(0xffffffffu, rs0, 2);
        rs1 += __shfl_xor_sync(0xffffffffu, rs1, 1);
        rs1 += __shfl_xor_sync(0xffffffffu, rs1, 2);
        l0 = l0 * al0 + rs0;
        l1 = l1 * al1 + rs1;
        m0 = mn0; m1 = mn1;
#pragma unroll
        for (int j = 0; j < 8; j++) {
            o[j][0] *= al0; o[j][1] *= al0;
            o[j][2] *= al1; o[j][3] *= al1;
        }

#pragma unroll
        for (int kc = 0; kc < 4; kc++) {
#pragma unroll
            for (int jdp = 0; jdp < 4; jdp++) {
                uint32_t toff = (uint32_t)(kc * 16 * FP + jdp * 16) * 2;
                uint32_t vh[4], vl[4];
                ldm4t(vh, khb + offV + toff);
                ldm4t(vl, klb + offV + toff);
                mma16816(o[2 * jdp],     pah[kc], vh[0], vh[1]);
                mma16816(o[2 * jdp],     pah[kc], vl[0], vl[1]);
                mma16816(o[2 * jdp],     pal[kc], vh[0], vh[1]);
                mma16816(o[2 * jdp + 1], pah[kc], vh[2], vh[3]);
                mma16816(o[2 * jdp + 1], pah[kc], vl[2], vl[3]);
                mma16816(o[2 * jdp + 1], pal[kc], vh[2], vh[3]);
            }
        }
        __syncthreads();
    }

    // ---- epilogue: split-bf16 writes in the natural zc layout (coalesced) ----
    float inv0 = 1.f / l0, inv1 = 1.f / l1;
    int n0 = rb * 64 + ar, n1 = n0 + 8;
    size_t row0 = (size_t)(h * 64 + (n0 >> 5)) * N_TOK + (n0 & 31) * 64;
    size_t row1 = (size_t)(h * 64 + (n1 >> 5)) * N_TOK + (n1 & 31) * 64;
#pragma unroll
    for (int jd = 0; jd < 8; jd++) {
        int d = jd * 8 + ac;
        float v0 = o[jd][0] * inv0, v1 = o[jd][1] * inv0;
        bf h0 = __float2bfloat16(v0), h1 = __float2bfloat16(v1);
        *(uint32_t*)&zch[row0 + d] = ((uint32_t)*(uint16_t*)&h1 << 16) | *(uint16_t*)&h0;
        bf e0 = __float2bfloat16(v0 - __bfloat162float(h0));
        bf e1 = __float2bfloat16(v1 - __bfloat162float(h1));
        *(uint32_t*)&zcl[row0 + d] = ((uint32_t)*(uint16_t*)&e1 << 16) | *(uint16_t*)&e0;
        float w0 = o[jd][2] * inv1, w1 = o[jd][3] * inv1;
        bf j0 = __float2bfloat16(w0), j1 = __float2bfloat16(w1);
        *(uint32_t*)&zch[row1 + d] = ((uint32_t)*(uint16_t*)&j1 << 16) | *(uint16_t*)&j0;
        bf k0 = __float2bfloat16(w0 - __bfloat162float(j0));
        bf k1 = __float2bfloat16(w1 - __bfloat162float(j1));
        *(uint32_t*)&zcl[row1 + d] = ((uint32_t)*(uint16_t*)&k1 << 16) | *(uint16_t*)&k0;
    }
}

// ---------------- fused residual (+bias) + LayerNorm (+optional split out) ----------------
template <bool SPLIT>
__global__ void add_ln(const float* __restrict__ A, const float* __restrict__ Bd,
                       const float* __restrict__ g, const float* __restrict__ bb,
                       const float* __restrict__ extra, float* __restrict__ out,
                       bf* __restrict__ oh, bf* __restrict__ ol) {
    __shared__ float red[8];
    int n = blockIdx.x, tid = threadIdx.x;
    float loc[3];
    float s = 0.f;
#pragma unroll
    for (int i = 0; i < 3; i++) {
        int e = tid + i * 256;
        float v = A[(size_t)n * EDIM + e] + Bd[(size_t)n * EDIM + e];
        if (extra) v += extra[e];
        loc[i] = v; s += v;
    }
#pragma unroll
    for (int o = 16; o; o >>= 1) s += __shfl_xor_sync(0xffffffffu, s, o);
    if ((tid & 31) == 0) red[tid >> 5] = s;
    __syncthreads();
    if (tid < 32) {
        float t = (tid < 8) ? red[tid] : 0.f;
#pragma unroll
        for (int o = 4; o; o >>= 1) t += __shfl_xor_sync(0xffffffffu, t, o);
        if (tid == 0) red[0] = t;
    }
    __syncthreads();
    float mu = red[0] * (1.f / 768.f);
    __syncthreads();
    float sq = 0.f;
#pragma unroll
    for (int i = 0; i < 3; i++) { float d = loc[i] - mu; sq += d * d; }
#pragma unroll
    for (int o = 16; o; o >>= 1) sq += __shfl_xor_sync(0xffffffffu, sq, o);
    if ((tid & 31) == 0) red[tid >> 5] = sq;
    __syncthreads();
    if (tid < 32) {
        float t = (tid < 8) ? red[tid] : 0.f;
#pragma unroll
        for (int o = 4; o; o >>= 1) t += __shfl_xor_sync(0xffffffffu, t, o);
        if (tid == 0) red[0] = t;
    }
    __syncthreads();
    float var = red[0] * (1.f / 768.f);
    float inv = rsqrtf(var + 1e-5f);
#pragma unroll
    for (int i = 0; i < 3; i++) {
        int e = tid + i * 256;
        float v = (loc[i] - mu) * inv * g[e] + bb[e];
        size_t go = (size_t)n * EDIM + e;
        out[go] = v;
        if (SPLIT) split1(v, &oh[go], &ol[go]);
    }
}

// ---------------- launch ----------------
extern "C" void kernel_launch(void* const* d_in, const int* in_sizes, int n_in,
                              void* d_out, int out_size) {
    const float* tokens = (const float*)d_in[0];
    const float* wq = (const float*)d_in[1];
    const float* wo = (const float*)d_in[2];
    const float* g1 = (const float*)d_in[3];
    const float* b1 = (const float*)d_in[4];
    const float* fw = (const float*)d_in[5];
    const float* fb = (const float*)d_in[6];
    const float* g2 = (const float*)d_in[7];
    const float* b2 = (const float*)d_in[8];
    float* out = (float*)d_out;

    float *x, *mh, *l1, *ffn;
    bf *xh, *xl, *qh, *ql, *l1h, *l1l, *zch, *zcl;
    bf *wqh, *wql, *woh, *wol, *fwh, *fwl;
    cudaGetSymbolAddress((void**)&x, g_x);     cudaGetSymbolAddress((void**)&mh, g_mh);
    cudaGetSymbolAddress((void**)&l1, g_l1);   cudaGetSymbolAddress((void**)&ffn, g_ffn);
    cudaGetSymbolAddress((void**)&xh, g_xh);   cudaGetSymbolAddress((void**)&xl, g_xl);
    cudaGetSymbolAddress((void**)&qh, g_qh);   cudaGetSymbolAddress((void**)&ql, g_ql);
    cudaGetSymbolAddress((void**)&l1h, g_l1h); cudaGetSymbolAddress((void**)&l1l, g_l1l);
    cudaGetSymbolAddress((void**)&zch, g_zch); cudaGetSymbolAddress((void**)&zcl, g_zcl);
    cudaGetSymbolAddress((void**)&wqh, g_wqh); cudaGetSymbolAddress((void**)&wql, g_wql);
    cudaGetSymbolAddress((void**)&woh, g_woh); cudaGetSymbolAddress((void**)&wol, g_wol);
    cudaGetSymbolAddress((void**)&fwh, g_fwh); cudaGetSymbolAddress((void**)&fwl, g_fwl);

    cudaFuncSetAttribute((const void*)gemm_bf<0, false>,
                         cudaFuncAttributeMaxDynamicSharedMemorySize, GEMM_SMEM_MAX);
    cudaFuncSetAttribute((const void*)gemm_bf<0, true>,
                         cudaFuncAttributeMaxDynamicSharedMemorySize, GEMM_SMEM_MAX);
    cudaFuncSetAttribute((const void*)gemm_bf<1, false>,
                         cudaFuncAttributeMaxDynamicSharedMemorySize, GEMM_SMEM_MAX);
    cudaFuncSetAttribute((const void*)flash_bf,
                         cudaFuncAttributeMaxDynamicSharedMemorySize, FLASH_SMEM);

    prep_wq<<<12 * LAYW / 256, 256>>>(wq, wqh, wql);
    split_arr<<<12 * LAYW / 256, 256>>>(wo, woh, wol);
    split_arr<<<12 * LAYW / 256, 256>>>(fw, fwh, fwl);
    add_pe_kernel<<<(N_TOK * EDIM) / 256, 256>>>(tokens, x, xh, xl);

    for (int step = 0; step < 13; step++) {
        int lidx = (step == 0) ? 0 : step - 1;
        const bf* wqh_l = wqh + (size_t)lidx * LAYW;
        const bf* wql_l = wql + (size_t)lidx * LAYW;
        const bf* woh_l = woh + (size_t)lidx * LAYW;
        const bf* wol_l = wol + (size_t)lidx * LAYW;
        const bf* fwh_l = fwh + (size_t)lidx * LAYW;
        const bf* fwl_l = fwl + (size_t)lidx * LAYW;

        // q = x @ wqfT^T -> split bf16 output directly   [2048x768], NT
        gemm_bf<0, true><<<dim3(EDIM / 128, N_TOK / 128), 256, GEMM_SMEM_MAX>>>(
            xh, xl, wqh_l, wql_l, nullptr, qh, ql, N_TOK, EDIM, EDIM);

        // attention -> zch/zcl in natural zc layout (coalesced split writes)
        flash_bf<<<dim3(32, HEADS), 128, FLASH_SMEM>>>(qh, ql, zch, zcl);

        // mh = wo @ zc   [768x2048], NN (consumes zc K-major directly, no transpose)
        gemm_bf<1, false><<<dim3(N_TOK / 128, EDIM / 128), 256, GEMM_SMEM_MAX>>>(
            woh_l, wol_l, zch, zcl, mh, nullptr, nullptr, EDIM, N_TOK, EDIM);

        add_ln<true><<<N_TOK, 256>>>(x, mh, g1 + lidx * EDIM, b1 + lidx * EDIM,
                                     nullptr, l1, l1h, l1l);

        // ffn = l1 @ fw^T (bias folded into next add_ln)   [2048x768], NT
        gemm_bf<0, false><<<dim3(EDIM / 128, N_TOK / 128), 256, GEMM_SMEM_MAX>>>(
            l1h, l1l, fwh_l, fwl_l, ffn, nullptr, nullptr, N_TOK, EDIM, EDIM);

        if (step == 12)
            add_ln<false><<<N_TOK, 256>>>(l1, ffn, g2 + lidx * EDIM, b2 + lidx * EDIM,
                                          fb + lidx * EDIM, out, nullptr, nullptr);
        else
            add_ln<true><<<N_TOK, 256>>>(l1, ffn, g2 + lidx * EDIM, b2 + lidx * EDIM,
                                         fb + lidx * EDIM, x, xh, xl);
    }
}

// round 11
// speedup vs baseline: 1.1492x; 1.0838x over previous
#include <cuda_runtime.h>
#include <cuda_bf16.h>
#include <mma.h>
#include <cstdint>
using namespace nvcuda;
typedef __nv_bfloat16 bf;

#define N_TOK 2048
#define EDIM  768
#define HEADS 12
#define DH    64
#define LAYW  (EDIM * EDIM)

// fp32 scratch
__device__ float g_x[N_TOK * EDIM], g_mh[EDIM * N_TOK], g_l1[N_TOK * EDIM], g_ffn[N_TOK * EDIM];
// bf16 split activations
__device__ bf g_xh[N_TOK * EDIM], g_xl[N_TOK * EDIM], g_qh[N_TOK * EDIM], g_ql[N_TOK * EDIM],
              g_l1h[N_TOK * EDIM], g_l1l[N_TOK * EDIM], g_zch[EDIM * N_TOK], g_zcl[EDIM * N_TOK];
// bf16 split weights, all 12 layers
__device__ bf g_wqh[12 * LAYW], g_wql[12 * LAYW], g_woh[12 * LAYW], g_wol[12 * LAYW],
              g_fwh[12 * LAYW], g_fwl[12 * LAYW];

// ---------------- helpers ----------------
__device__ __forceinline__ uint32_t smem_u32(const void* p) {
    uint32_t a;
    asm("{ .reg .u64 t; cvta.to.shared.u64 t, %1; cvt.u32.u64 %0, t; }" : "=r"(a) : "l"(p));
    return a;
}
__device__ __forceinline__ uint32_t pk2(float lo, float hi) {
    uint32_t r;
    asm("cvt.rn.bf16x2.f32 %0, %1, %2;" : "=r"(r) : "f"(hi), "f"(lo));
    return r;
}
__device__ __forceinline__ void split1(float v, bf* h, bf* l) {
    bf hh = __float2bfloat16(v);
    *h = hh;
    *l = __float2bfloat16(v - __bfloat162float(hh));
}
__device__ __forceinline__ void mma16816(float* c, const uint32_t* a, uint32_t b0, uint32_t b1) {
    asm volatile("mma.sync.aligned.m16n8k16.row.col.f32.bf16.bf16.f32 "
                 "{%0,%1,%2,%3}, {%4,%5,%6,%7}, {%8,%9}, {%0,%1,%2,%3};"
                 : "+f"(c[0]), "+f"(c[1]), "+f"(c[2]), "+f"(c[3])
                 : "r"(a[0]), "r"(a[1]), "r"(a[2]), "r"(a[3]), "r"(b0), "r"(b1));
}
__device__ __forceinline__ void ldm4(uint32_t* r, uint32_t addr) {
    asm volatile("ldmatrix.sync.aligned.m8n8.x4.shared.b16 {%0,%1,%2,%3}, [%4];"
                 : "=r"(r[0]), "=r"(r[1]), "=r"(r[2]), "=r"(r[3]) : "r"(addr));
}
__device__ __forceinline__ void ldm4t(uint32_t* r, uint32_t addr) {
    asm volatile("ldmatrix.sync.aligned.m8n8.x4.trans.shared.b16 {%0,%1,%2,%3}, [%4];"
                 : "=r"(r[0]), "=r"(r[1]), "=r"(r[2]), "=r"(r[3]) : "r"(addr));
}
#define CPA(dst, src) asm volatile("cp.async.cg.shared.global [%0], [%1], 16;" :: "r"(dst), "l"(src))
#define CPC()  asm volatile("cp.async.commit_group;" ::: "memory")
#define CPW0() asm volatile("cp.async.wait_group 0;" ::: "memory")
#define CPW1() asm volatile("cp.async.wait_group 1;" ::: "memory")

// ---------------- prep kernels ----------------
// One kernel splits all three weight stacks (wq with its head-transpose indexing).
__global__ void prep_all(const float* __restrict__ wq, const float* __restrict__ wo,
                         const float* __restrict__ fw,
                         bf* __restrict__ wqh, bf* __restrict__ wql,
                         bf* __restrict__ woh, bf* __restrict__ wol,
                         bf* __restrict__ fwh, bf* __restrict__ fwl) {
    int idx = blockIdx.x * 256 + threadIdx.x;          // 12*768*768
    int lay = idx / LAYW, r = idx % LAYW;
    int n = r / EDIM, e = r % EDIM;
    float vq = wq[(size_t)lay * LAYW + (n >> 6) * (EDIM * DH) + e * DH + (n & 63)];
    split1(vq, &wqh[idx], &wql[idx]);
    split1(wo[idx], &woh[idx], &wol[idx]);
    split1(fw[idx], &fwh[idx], &fwl[idx]);
}
__global__ void add_pe_kernel(const float* __restrict__ tokens, float* __restrict__ x,
                              bf* __restrict__ xh, bf* __restrict__ xl) {
    int idx = blockIdx.x * 256 + threadIdx.x;
    int e = idx % EDIM, n = idx / EDIM, s = n & 511;
    float p = (e < 384) ? 10000.0f : 10001.0f;
    float ang = (float)s / p;
    float pe = (e & 1) ? cosf(ang) : sinf(ang);
    float v = tokens[idx] + pe;
    x[idx] = v;
    split1(v, &xh[idx], &xl[idx]);
}

// ---------------- bf16-split GEMM ----------------
// BMODE 0 (NT): D[M,N] = A[M,K] * B[N,K]^T   (B row-major [N,K])
// BMODE 1 (NN): D[M,N] = A[M,K] * B[K,N]     (B row-major [K,N] -- zc layout)
// 128x128 CTA tile, 8 warps (4x2), warp 32x64, K chunk 64, double-buffered cp.async.
#define GP 72
#define BPN 136
#define ABUFE (128 * GP)
template <int BMODE> struct GCfg {
    static const int BBUFE = (BMODE ? 64 * BPN : 128 * GP);
    static const int STAGE = 2 * ABUFE + 2 * BBUFE;
};
#define GEMM_SMEM_MAX (2 * (2 * ABUFE + 2 * ABUFE) * 2)   // 147456

template <int BMODE>
__device__ __forceinline__ void gemm_load(uint32_t sb, int b, const bf* Ah, const bf* Al,
                                          const bf* Bh, const bf* Bl,
                                          int bm, int bn, int N, int K, int k0, int tid) {
    const int STAGE = GCfg<BMODE>::STAGE;
    const int BBUFE = GCfg<BMODE>::BBUFE;
    uint32_t base = sb + (uint32_t)(b * STAGE) * 2;
#pragma unroll
    for (int m = 0; m < 4; m++) {
        int task = tid + 256 * m;
        int r = task >> 3, gc = (task & 7) * 8;
        uint32_t so = (uint32_t)(r * GP + gc) * 2;
        size_t ga = (size_t)(bm + r) * K + k0 + gc;
        CPA(base + so,             Ah + ga);
        CPA(base + ABUFE * 2 + so, Al + ga);
    }
    if (BMODE == 0) {
#pragma unroll
        for (int m = 0; m < 4; m++) {
            int task = tid + 256 * m;
            int r = task >> 3, gc = (task & 7) * 8;
            uint32_t so = (uint32_t)(r * GP + gc) * 2;
            size_t gb = (size_t)(bn + r) * K + k0 + gc;
            CPA(base + ABUFE * 4 + so,               Bh + gb);
            CPA(base + (ABUFE * 4 + BBUFE * 2) + so, Bl + gb);
        }
    } else {
#pragma unroll
        for (int m = 0; m < 4; m++) {
            int task = tid + 256 * m;
            int r = task >> 4, gc = (task & 15) * 8;
            uint32_t so = (uint32_t)(r * BPN + gc) * 2;
            size_t gb = (size_t)(k0 + r) * N + bn + gc;
            CPA(base + ABUFE * 4 + so,               Bh + gb);
            CPA(base + (ABUFE * 4 + BBUFE * 2) + so, Bl + gb);
        }
    }
    CPC();
}

template <int BMODE, bool OUTSPLIT>
__global__ void __launch_bounds__(256, 1)
gemm_bf(const bf* __restrict__ Ah, const bf* __restrict__ Al,
        const bf* __restrict__ Bh, const bf* __restrict__ Bl,
        float* __restrict__ C, bf* __restrict__ Ch, bf* __restrict__ Cl,
        int M, int N, int K) {
    const int STAGE = GCfg<BMODE>::STAGE;
    const int BBUFE = GCfg<BMODE>::BBUFE;
    extern __shared__ bf ds[];
    uint32_t sb = smem_u32(ds);
    int tid = threadIdx.x, wid = tid >> 5;
    int bm = blockIdx.y * 128, bn = blockIdx.x * 128;
    int wm = (wid >> 1) * 32, wn = (wid & 1) * 64;

    wmma::fragment<wmma::accumulator, 16, 16, 16, float> acc[2][4];
#pragma unroll
    for (int i = 0; i < 2; i++)
#pragma unroll
        for (int j = 0; j < 4; j++) wmma::fill_fragment(acc[i][j], 0.f);

    const int NCH = K / 64;
    gemm_load<BMODE>(sb, 0, Ah, Al, Bh, Bl, bm, bn, N, K, 0, tid);

    for (int c = 0; c < NCH; c++) {
        if (c + 1 < NCH) {
            gemm_load<BMODE>(sb, (c + 1) & 1, Ah, Al, Bh, Bl, bm, bn, N, K, (c + 1) * 64, tid);
            CPW1();
        } else {
            CPW0();
        }
        __syncthreads();
        bf* Ahs = ds + (size_t)(c & 1) * STAGE;
        bf* Als = Ahs + ABUFE;
        bf* Bhs = Ahs + 2 * ABUFE;
        bf* Bls = Bhs + BBUFE;
#pragma unroll
        for (int kc = 0; kc < 4; kc++) {
            wmma::fragment<wmma::matrix_a, 16, 16, 16, bf, wmma::row_major> ah2[2], al2[2];
#pragma unroll
            for (int i = 0; i < 2; i++) {
                wmma::load_matrix_sync(ah2[i], &Ahs[(wm + 16 * i) * GP + kc * 16], GP);
                wmma::load_matrix_sync(al2[i], &Als[(wm + 16 * i) * GP + kc * 16], GP);
            }
#pragma unroll
            for (int j = 0; j < 4; j++) {
                if (BMODE == 0) {
                    wmma::fragment<wmma::matrix_b, 16, 16, 16, bf, wmma::col_major> bh2, bl2;
                    wmma::load_matrix_sync(bh2, &Bhs[(wn + 16 * j) * GP + kc * 16], GP);
                    wmma::load_matrix_sync(bl2, &Bls[(wn + 16 * j) * GP + kc * 16], GP);
#pragma unroll
                    for (int i = 0; i < 2; i++) {
                        wmma::mma_sync(acc[i][j], ah2[i], bh2, acc[i][j]);
                        wmma::mma_sync(acc[i][j], ah2[i], bl2, acc[i][j]);
                        wmma::mma_sync(acc[i][j], al2[i], bh2, acc[i][j]);
                    }
                } else {
                    wmma::fragment<wmma::matrix_b, 16, 16, 16, bf, wmma::row_major> bh2, bl2;
                    wmma::load_matrix_sync(bh2, &Bhs[(kc * 16) * BPN + wn + 16 * j], BPN);
                    wmma::load_matrix_sync(bl2, &Bls[(kc * 16) * BPN + wn + 16 * j], BPN);
#pragma unroll
                    for (int i = 0; i < 2; i++) {
                        wmma::mma_sync(acc[i][j], ah2[i], bh2, acc[i][j]);
                        wmma::mma_sync(acc[i][j], ah2[i], bl2, acc[i][j]);
                        wmma::mma_sync(acc[i][j], al2[i], bh2, acc[i][j]);
                    }
                }
            }
        }
        __syncthreads();
    }

    if (!OUTSPLIT) {
#pragma unroll
        for (int i = 0; i < 2; i++)
#pragma unroll
            for (int j = 0; j < 4; j++)
                wmma::store_matrix_sync(&C[(size_t)(bm + wm + 16 * i) * N + bn + wn + 16 * j],
                                        acc[i][j], N, wmma::mem_row_major);
    } else {
        float* cs = (float*)ds;
#pragma unroll
        for (int i = 0; i < 2; i++)
#pragma unroll
            for (int j = 0; j < 4; j++)
                wmma::store_matrix_sync(&cs[(wm + 16 * i) * 128 + wn + 16 * j],
                                        acc[i][j], 128, wmma::mem_row_major);
        __syncthreads();
#pragma unroll
        for (int m = 0; m < 64; m++) {
            int idx = tid + 256 * m;
            int r = idx >> 7, cc = idx & 127;
            size_t go = (size_t)(bm + r) * N + bn + cc;
            split1(cs[r * 128 + cc], &Ch[go], &Cl[go]);
        }
    }
}

// ---------------- flash attention (q==k==v), pre-split bf16, cp.async pipeline ----------------
// PV uses 2-term split (Ph*Vh + Ph*Vl); the Pl*Vh correction is dropped: P in [0,1]
// sums to 1, so its bf16 rounding error enters O incoherently (~1e-4/layer).
#define FP 72
#define FQH 0
#define FQL (64 * FP)
#define FKH(b) (2 * 64 * FP + (b) * 2 * 64 * FP)
#define FKL(b) (FKH(b) + 64 * FP)
#define FLASH_SMEM (6 * 64 * FP * 2)

__global__ void __launch_bounds__(128, 3)
flash_bf(const bf* __restrict__ Qh, const bf* __restrict__ Ql,
         bf* __restrict__ zch, bf* __restrict__ zcl) {
    extern __shared__ bf ds[];
    uint32_t sb = smem_u32(ds);
    int tid = threadIdx.x, lane = tid & 31, wid = tid >> 5;
    int h = blockIdx.y, rb = blockIdx.x;
    size_t hoff = (size_t)h * DH;

#pragma unroll
    for (int m = 0; m < 4; m++) {
        int task = tid + 128 * m;
        int r = task >> 3, gc = (task & 7) * 8;
        size_t go = (size_t)(rb * 64 + r) * EDIM + hoff + gc;
        CPA(sb + (FQH + r * FP + gc) * 2, Qh + go);
        CPA(sb + (FQL + r * FP + gc) * 2, Ql + go);
        size_t gk = (size_t)r * EDIM + hoff + gc;
        CPA(sb + (FKH(0) + r * FP + gc) * 2, Qh + gk);
        CPA(sb + (FKL(0) + r * FP + gc) * 2, Ql + gk);
    }
    CPC(); CPW0();
    __syncthreads();

    int ar = wid * 16 + (lane >> 2);
    int ac = 2 * (lane & 3);
    uint32_t qah[4][4], qal[4][4];
#pragma unroll
    for (int kc = 0; kc < 4; kc++) {
        int cb = kc * 16 + ac;
        qah[kc][0] = *(uint32_t*)&ds[FQH + (ar)     * FP + cb];
        qah[kc][1] = *(uint32_t*)&ds[FQH + (ar + 8) * FP + cb];
        qah[kc][2] = *(uint32_t*)&ds[FQH + (ar)     * FP + cb + 8];
        qah[kc][3] = *(uint32_t*)&ds[FQH + (ar + 8) * FP + cb + 8];
        qal[kc][0] = *(uint32_t*)&ds[FQL + (ar)     * FP + cb];
        qal[kc][1] = *(uint32_t*)&ds[FQL + (ar + 8) * FP + cb];
        qal[kc][2] = *(uint32_t*)&ds[FQL + (ar)     * FP + cb + 8];
        qal[kc][3] = *(uint32_t*)&ds[FQL + (ar + 8) * FP + cb + 8];
    }

    float m0 = -1e30f, m1 = -1e30f, l0 = 0.f, l1 = 0.f;
    float o[8][4];
#pragma unroll
    for (int j = 0; j < 8; j++)
#pragma unroll
        for (int c = 0; c < 4; c++) o[j][c] = 0.f;

    int g = lane >> 3, i8 = lane & 7;
    uint32_t offS = (uint32_t)(((g >> 1) * 8 + i8) * FP + (g & 1) * 8) * 2;
    uint32_t offV = (uint32_t)(((g & 1) * 8 + i8) * FP + (g >> 1) * 8) * 2;

    for (int ct = 0; ct < 32; ct++) {
        if (ct < 31) {
            int b = (ct + 1) & 1;
#pragma unroll
            for (int m = 0; m < 4; m++) {
                int task = tid + 128 * m;
                int r = task >> 3, gc = (task & 7) * 8;
                size_t gk = (size_t)((ct + 1) * 64 + r) * EDIM + hoff + gc;
                CPA(sb + (FKH(b) + r * FP + gc) * 2, Qh + gk);
                CPA(sb + (FKL(b) + r * FP + gc) * 2, Ql + gk);
            }
            CPC(); CPW1();
        } else {
            CPW0();
        }
        __syncthreads();
        uint32_t khb = sb + FKH(ct & 1) * 2, klb = sb + FKL(ct & 1) * 2;

        float sacc[8][4];
#pragma unroll
        for (int j = 0; j < 8; j++)
#pragma unroll
            for (int c = 0; c < 4; c++) sacc[j][c] = 0.f;
#pragma unroll
        for (int kc = 0; kc < 4; kc++) {
#pragma unroll
            for (int jp = 0; jp < 4; jp++) {
                uint32_t toff = (uint32_t)(jp * 16 * FP + kc * 16) * 2;
                uint32_t bh[4], bl[4];
                ldm4(bh, khb + offS + toff);
                ldm4(bl, klb + offS + toff);
                mma16816(sacc[2 * jp],     qah[kc], bh[0], bh[1]);
                mma16816(sacc[2 * jp],     qah[kc], bl[0], bl[1]);
                mma16816(sacc[2 * jp],     qal[kc], bh[0], bh[1]);
                mma16816(sacc[2 * jp + 1], qah[kc], bh[2], bh[3]);
                mma16816(sacc[2 * jp + 1], qah[kc], bl[2], bl[3]);
                mma16816(sacc[2 * jp + 1], qal[kc], bh[2], bh[3]);
            }
        }

        float mx0 = -1e30f, mx1 = -1e30f;
#pragma unroll
        for (int j = 0; j < 8; j++) {
#pragma unroll
            for (int c = 0; c < 4; c++) sacc[j][c] *= 0.125f;
            mx0 = fmaxf(mx0, fmaxf(sacc[j][0], sacc[j][1]));
            mx1 = fmaxf(mx1, fmaxf(sacc[j][2], sacc[j][3]));
        }
        mx0 = fmaxf(mx0, __shfl_xor_sync(0xffffffffu, mx0, 1));
        mx0 = fmaxf(mx0, __shfl_xor_sync(0xffffffffu, mx0, 2));
        mx1 = fmaxf(mx1, __shfl_xor_sync(0xffffffffu, mx1, 1));
        mx1 = fmaxf(mx1, __shfl_xor_sync(0xffffffffu, mx1, 2));
        float mn0 = fmaxf(m0, mx0), mn1 = fmaxf(m1, mx1);
        float al0 = __expf(m0 - mn0), al1 = __expf(m1 - mn1);

        float rs0 = 0.f, rs1 = 0.f;
        uint32_t pah[4][4];
#pragma unroll
        for (int j = 0; j < 8; j++) {
            float p0 = __expf(sacc[j][0] - mn0);
            float p1 = __expf(sacc[j][1] - mn0);
            float p2 = __expf(sacc[j][2] - mn1);
            float p3 = __expf(sacc[j][3] - mn1);
            rs0 += p0 + p1; rs1 += p2 + p3;
            int kc = j >> 1, off = (j & 1) * 2;
            pah[kc][off]     = pk2(p0, p1);
            pah[kc][off + 1] = pk2(p2, p3);
        }
        rs0 += __shfl_xor_sync(0xffffffffu, rs0, 1);
        rs0 += __shfl_xor_sync(0xffffffffu, rs0, 2);
        rs1 += __shfl_xor_sync(0xffffffffu, rs1, 1);
        rs1 += __shfl_xor_sync(0xffffffffu, rs1, 2);
        l0 = l0 * al0 + rs0;
        l1 = l1 * al1 + rs1;
        m0 = mn0; m1 = mn1;
#pragma unroll
        for (int j = 0; j < 8; j++) {
            o[j][0] *= al0; o[j][1] *= al0;
            o[j][2] *= al1; o[j][3] *= al1;
        }

#pragma unroll
        for (int kc = 0; kc < 4; kc++) {
#pragma unroll
            for (int jdp = 0; jdp < 4; jdp++) {
                uint32_t toff = (uint32_t)(kc * 16 * FP + jdp * 16) * 2;
                uint32_t vh[4], vl[4];
                ldm4t(vh, khb + offV + toff);
                ldm4t(vl, klb + offV + toff);
                mma16816(o[2 * jdp],     pah[kc], vh[0], vh[1]);
                mma16816(o[2 * jdp],     pah[kc], vl[0], vl[1]);
                mma16816(o[2 * jdp + 1], pah[kc], vh[2], vh[3]);
                mma16816(o[2 * jdp + 1], pah[kc], vl[2], vl[3]);
            }
        }
        __syncthreads();
    }

    // ---- epilogue: split-bf16 writes in the natural zc layout (coalesced) ----
    float inv0 = 1.f / l0, inv1 = 1.f / l1;
    int n0 = rb * 64 + ar, n1 = n0 + 8;
    size_t row0 = (size_t)(h * 64 + (n0 >> 5)) * N_TOK + (n0 & 31) * 64;
    size_t row1 = (size_t)(h * 64 + (n1 >> 5)) * N_TOK + (n1 & 31) * 64;
#pragma unroll
    for (int jd = 0; jd < 8; jd++) {
        int d = jd * 8 + ac;
        float v0 = o[jd][0] * inv0, v1 = o[jd][1] * inv0;
        bf h0 = __float2bfloat16(v0), h1 = __float2bfloat16(v1);
        *(uint32_t*)&zch[row0 + d] = ((uint32_t)*(uint16_t*)&h1 << 16) | *(uint16_t*)&h0;
        bf e0 = __float2bfloat16(v0 - __bfloat162float(h0));
        bf e1 = __float2bfloat16(v1 - __bfloat162float(h1));
        *(uint32_t*)&zcl[row0 + d] = ((uint32_t)*(uint16_t*)&e1 << 16) | *(uint16_t*)&e0;
        float w0 = o[jd][2] * inv1, w1 = o[jd][3] * inv1;
        bf j0 = __float2bfloat16(w0), j1 = __float2bfloat16(w1);
        *(uint32_t*)&zch[row1 + d] = ((uint32_t)*(uint16_t*)&j1 << 16) | *(uint16_t*)&j0;
        bf k0 = __float2bfloat16(w0 - __bfloat162float(j0));
        bf k1 = __float2bfloat16(w1 - __bfloat162float(j1));
        *(uint32_t*)&zcl[row1 + d] = ((uint32_t)*(uint16_t*)&k1 << 16) | *(uint16_t*)&k0;
    }
}

// ---------------- fused residual (+bias) + LayerNorm (+optional split out) ----------------
template <bool SPLIT>
__global__ void add_ln(const float* __restrict__ A, const float* __restrict__ Bd,
                       const float* __restrict__ g, const float* __restrict__ bb,
                       const float* __restrict__ extra, float* __restrict__ out,
                       bf* __restrict__ oh, bf* __restrict__ ol) {
    __shared__ float red[8];
    int n = blockIdx.x, tid = threadIdx.x;
    float loc[3];
    float s = 0.f;
#pragma unroll
    for (int i = 0; i < 3; i++) {
        int e = tid + i * 256;
        float v = A[(size_t)n * EDIM + e] + Bd[(size_t)n * EDIM + e];
        if (extra) v += extra[e];
        loc[i] = v; s += v;
    }
#pragma unroll
    for (int o = 16; o; o >>= 1) s += __shfl_xor_sync(0xffffffffu, s, o);
    if ((tid & 31) == 0) red[tid >> 5] = s;
    __syncthreads();
    if (tid < 32) {
        float t = (tid < 8) ? red[tid] : 0.f;
#pragma unroll
        for (int o = 4; o; o >>= 1) t += __shfl_xor_sync(0xffffffffu, t, o);
        if (tid == 0) red[0] = t;
    }
    __syncthreads();
    float mu = red[0] * (1.f / 768.f);
    __syncthreads();
    float sq = 0.f;
#pragma unroll
    for (int i = 0; i < 3; i++) { float d = loc[i] - mu; sq += d * d; }
#pragma unroll
    for (int o = 16; o; o >>= 1) sq += __shfl_xor_sync(0xffffffffu, sq, o);
    if ((tid & 31) == 0) red[tid >> 5] = sq;
    __syncthreads();
    if (tid < 32) {
        float t = (tid < 8) ? red[tid] : 0.f;
#pragma unroll
        for (int o = 4; o; o >>= 1) t += __shfl_xor_sync(0xffffffffu, t, o);
        if (tid == 0) red[0] = t;
    }
    __syncthreads();
    float var = red[0] * (1.f / 768.f);
    float inv = rsqrtf(var + 1e-5f);
#pragma unroll
    for (int i = 0; i < 3; i++) {
        int e = tid + i * 256;
        float v = (loc[i] - mu) * inv * g[e] + bb[e];
        size_t go = (size_t)n * EDIM + e;
        out[go] = v;
        if (SPLIT) split1(v, &oh[go], &ol[go]);
    }
}

// ---------------- launch ----------------
extern "C" void kernel_launch(void* const* d_in, const int* in_sizes, int n_in,
                              void* d_out, int out_size) {
    const float* tokens = (const float*)d_in[0];
    const float* wq = (const float*)d_in[1];
    const float* wo = (const float*)d_in[2];
    const float* g1 = (const float*)d_in[3];
    const float* b1 = (const float*)d_in[4];
    const float* fw = (const float*)d_in[5];
    const float* fb = (const float*)d_in[6];
    const float* g2 = (const float*)d_in[7];
    const float* b2 = (const float*)d_in[8];
    float* out = (float*)d_out;

    float *x, *mh, *l1, *ffn;
    bf *xh, *xl, *qh, *ql, *l1h, *l1l, *zch, *zcl;
    bf *wqh, *wql, *woh, *wol, *fwh, *fwl;
    cudaGetSymbolAddress((void**)&x, g_x);     cudaGetSymbolAddress((void**)&mh, g_mh);
    cudaGetSymbolAddress((void**)&l1, g_l1);   cudaGetSymbolAddress((void**)&ffn, g_ffn);
    cudaGetSymbolAddress((void**)&xh, g_xh);   cudaGetSymbolAddress((void**)&xl, g_xl);
    cudaGetSymbolAddress((void**)&qh, g_qh);   cudaGetSymbolAddress((void**)&ql, g_ql);
    cudaGetSymbolAddress((void**)&l1h, g_l1h); cudaGetSymbolAddress((void**)&l1l, g_l1l);
    cudaGetSymbolAddress((void**)&zch, g_zch); cudaGetSymbolAddress((void**)&zcl, g_zcl);
    cudaGetSymbolAddress((void**)&wqh, g_wqh); cudaGetSymbolAddress((void**)&wql, g_wql);
    cudaGetSymbolAddress((void**)&woh, g_woh); cudaGetSymbolAddress((void**)&wol, g_wol);
    cudaGetSymbolAddress((void**)&fwh, g_fwh); cudaGetSymbolAddress((void**)&fwl, g_fwl);

    cudaFuncSetAttribute((const void*)gemm_bf<0, false>,
                         cudaFuncAttributeMaxDynamicSharedMemorySize, GEMM_SMEM_MAX);
    cudaFuncSetAttribute((const void*)gemm_bf<0, true>,
                         cudaFuncAttributeMaxDynamicSharedMemorySize, GEMM_SMEM_MAX);
    cudaFuncSetAttribute((const void*)gemm_bf<1, false>,
                         cudaFuncAttributeMaxDynamicSharedMemorySize, GEMM_SMEM_MAX);
    cudaFuncSetAttribute((const void*)flash_bf,
                         cudaFuncAttributeMaxDynamicSharedMemorySize, FLASH_SMEM);

    prep_all<<<12 * LAYW / 256, 256>>>(wq, wo, fw, wqh, wql, woh, wol, fwh, fwl);
    add_pe_kernel<<<(N_TOK * EDIM) / 256, 256>>>(tokens, x, xh, xl);

    for (int step = 0; step < 13; step++) {
        int lidx = (step == 0) ? 0 : step - 1;
        const bf* wqh_l = wqh + (size_t)lidx * LAYW;
        const bf* wql_l = wql + (size_t)lidx * LAYW;
        const bf* woh_l = woh + (size_t)lidx * LAYW;
        const bf* wol_l = wol + (size_t)lidx * LAYW;
        const bf* fwh_l = fwh + (size_t)lidx * LAYW;
        const bf* fwl_l = fwl + (size_t)lidx * LAYW;

        // q = x @ wqfT^T -> split bf16 output directly   [2048x768], NT
        gemm_bf<0, true><<<dim3(EDIM / 128, N_TOK / 128), 256, GEMM_SMEM_MAX>>>(
            xh, xl, wqh_l, wql_l, nullptr, qh, ql, N_TOK, EDIM, EDIM);

        // attention -> zch/zcl in natural zc layout (coalesced split writes)
        flash_bf<<<dim3(32, HEADS), 128, FLASH_SMEM>>>(qh, ql, zch, zcl);

        // mh = wo @ zc   [768x2048], NN
        gemm_bf<1, false><<<dim3(N_TOK / 128, EDIM / 128), 256, GEMM_SMEM_MAX>>>(
            woh_l, wol_l, zch, zcl, mh, nullptr, nullptr, EDIM, N_TOK, EDIM);

        add_ln<true><<<N_TOK, 256>>>(x, mh, g1 + lidx * EDIM, b1 + lidx * EDIM,
                                     nullptr, l1, l1h, l1l);

        // ffn = l1 @ fw^T (bias folded into next add_ln)   [2048x768], NT
        gemm_bf<0, false><<<dim3(EDIM / 128, N_TOK / 128), 256, GEMM_SMEM_MAX>>>(
            l1h, l1l, fwh_l, fwl_l, ffn, nullptr, nullptr, N_TOK, EDIM, EDIM);

        if (step == 12)
            add_ln<false><<<N_TOK, 256>>>(l1, ffn, g2 + lidx * EDIM, b2 + lidx * EDIM,
                                          fb + lidx * EDIM, out, nullptr, nullptr);
        else
            add_ln<true><<<N_TOK, 256>>>(l1, ffn, g2 + lidx * EDIM, b2 + lidx * EDIM,
                                         fb + lidx * EDIM, x, xh, xl);
    }
}